// round 1
// baseline (speedup 1.0000x reference)
#include <cuda_runtime.h>
#include <cuda_bf16.h>
#include <math.h>

// ---------------- problem constants ----------------
#define B_   2
#define S_   512
#define M_   (B_ * S_)      // 1024 rows
#define D_   768
#define H_   12
#define DK_  64
#define DF_  3072
#define L_   12
#define V_   50257
#define EPS_ 1e-5f

// ---------------- scratch (device globals; no allocs allowed) ----------------
__device__ float g_x  [M_ * D_];   // residual stream
__device__ float g_h  [M_ * D_];   // layernorm output
__device__ float g_q  [M_ * D_];
__device__ float g_k  [M_ * D_];
__device__ float g_v  [M_ * D_];
__device__ float g_att[M_ * D_];   // attention output (pre-proj)
__device__ float g_ff [M_ * DF_];  // MLP hidden

// ---------------- embedding ----------------
__global__ void embed_kernel(const int* __restrict__ ids,
                             const float* __restrict__ tok,
                             const float* __restrict__ pos,
                             float* __restrict__ x) {
    int r = blockIdx.x;            // 0..M-1 ; r = b*S + s
    int s = r % S_;
    int id = ids[r];
    const float* t = tok + (size_t)id * D_;
    const float* p = pos + (size_t)s  * D_;
    float* xr = x + (size_t)r * D_;
    for (int d = threadIdx.x; d < D_; d += blockDim.x)
        xr[d] = t[d] + p[d];
}

// ---------------- layernorm (one block per row) ----------------
__global__ void ln_kernel(const float* __restrict__ x,
                          const float* __restrict__ g,
                          const float* __restrict__ b,
                          float* __restrict__ y) {
    __shared__ float red[256];
    int r = blockIdx.x;
    int tid = threadIdx.x;
    const float* xr = x + (size_t)r * D_;
    float* yr = y + (size_t)r * D_;

    float s = 0.f;
    for (int d = tid; d < D_; d += 256) s += xr[d];
    red[tid] = s; __syncthreads();
    for (int k = 128; k > 0; k >>= 1) {
        if (tid < k) red[tid] += red[tid + k];
        __syncthreads();
    }
    float mean = red[0] * (1.0f / D_);
    __syncthreads();

    float v = 0.f;
    for (int d = tid; d < D_; d += 256) { float t = xr[d] - mean; v += t * t; }
    red[tid] = v; __syncthreads();
    for (int k = 128; k > 0; k >>= 1) {
        if (tid < k) red[tid] += red[tid + k];
        __syncthreads();
    }
    float inv = rsqrtf(red[0] * (1.0f / D_) + EPS_);

    for (int d = tid; d < D_; d += 256)
        yr[d] = (xr[d] - mean) * inv * g[d] + b[d];
}

// ---------------- tiled SGEMM with fused epilogues ----------------
// C[M,N] = A[M,K] @ B + bias (+ resid | gelu)
// TRANSB=false: B is [K,N] row-major.  TRANSB=true: B is [N,K] row-major.
#define BM 64
#define BN 64
#define BK 16

enum { EPI_NONE = 0, EPI_RESID = 1, EPI_GELU = 2 };

template<int EPI, bool TRANSB>
__global__ __launch_bounds__(256)
void sgemm_kernel(const float* __restrict__ A, const float* __restrict__ B,
                  const float* __restrict__ bias, const float* __restrict__ resid,
                  float* __restrict__ C, int M, int N, int K) {
    // +4 pad keeps 16B alignment for vectorized LDS while dodging worst conflicts
    __shared__ float As[BK][BM + 4];
    __shared__ float Bs[BK][BN + 4];

    int tid = threadIdx.x;
    int tx = tid & 15;       // 0..15 -> n micro
    int ty = tid >> 4;       // 0..15 -> m micro
    int m0 = blockIdx.y * BM;
    int n0 = blockIdx.x * BN;

    float acc[4][4] = {};

    for (int k0 = 0; k0 < K; k0 += BK) {
        // load A tile (64x16): k fastest -> coalesced-ish along K
        #pragma unroll
        for (int i = 0; i < 4; i++) {
            int idx = tid + i * 256;
            int k = idx & (BK - 1);
            int m = idx / BK;
            int gm = m0 + m, gk = k0 + k;
            As[k][m] = (gm < M && gk < K) ? A[(size_t)gm * K + gk] : 0.f;
        }
        // load B tile (16x64)
        #pragma unroll
        for (int i = 0; i < 4; i++) {
            int idx = tid + i * 256;
            if (!TRANSB) {
                int n = idx & (BN - 1);
                int k = idx / BN;
                int gk = k0 + k, gn = n0 + n;
                Bs[k][n] = (gk < K && gn < N) ? B[(size_t)gk * N + gn] : 0.f;
            } else {
                int k = idx & (BK - 1);
                int n = idx / BK;
                int gk = k0 + k, gn = n0 + n;
                Bs[k][n] = (gn < N && gk < K) ? B[(size_t)gn * K + gk] : 0.f;
            }
        }
        __syncthreads();

        #pragma unroll
        for (int kk = 0; kk < BK; kk++) {
            float a[4], b[4];
            #pragma unroll
            for (int i = 0; i < 4; i++) a[i] = As[kk][ty * 4 + i];
            #pragma unroll
            for (int j = 0; j < 4; j++) b[j] = Bs[kk][tx * 4 + j];
            #pragma unroll
            for (int i = 0; i < 4; i++)
                #pragma unroll
                for (int j = 0; j < 4; j++)
                    acc[i][j] += a[i] * b[j];
        }
        __syncthreads();
    }

    #pragma unroll
    for (int i = 0; i < 4; i++) {
        int gm = m0 + ty * 4 + i;
        if (gm >= M) continue;
        #pragma unroll
        for (int j = 0; j < 4; j++) {
            int gn = n0 + tx * 4 + j;
            if (gn >= N) continue;
            float c = acc[i][j];
            if (bias) c += bias[gn];
            if (EPI == EPI_RESID) c += resid[(size_t)gm * N + gn];
            if (EPI == EPI_GELU)  c = 0.5f * c * (1.0f + erff(c * 0.70710678118654752f));
            C[(size_t)gm * N + gn] = c;
        }
    }
}

// ---------------- causal attention: one block per (q, h, b) ----------------
__global__ void attn_kernel(const float* __restrict__ q,
                            const float* __restrict__ k,
                            const float* __restrict__ v,
                            float* __restrict__ o) {
    int qi = blockIdx.x;
    int h  = blockIdx.y;
    int b  = blockIdx.z;
    int tid = threadIdx.x;                    // 128 threads

    __shared__ float qs[DK_];
    __shared__ float sc[S_];
    __shared__ float red[128];

    const float* qrow = q + ((size_t)(b * S_ + qi) * D_ + h * DK_);
    if (tid < DK_) qs[tid] = qrow[tid];
    __syncthreads();

    int Lq = qi + 1;   // causal length

    // scores
    for (int j = tid; j < Lq; j += 128) {
        const float* krow = k + ((size_t)(b * S_ + j) * D_ + h * DK_);
        float s = 0.f;
        #pragma unroll
        for (int d = 0; d < DK_; d++) s += qs[d] * krow[d];
        sc[j] = s * 0.125f;                   // 1/sqrt(64)
    }
    __syncthreads();

    // max
    float lm = -1e30f;
    for (int j = tid; j < Lq; j += 128) lm = fmaxf(lm, sc[j]);
    red[tid] = lm; __syncthreads();
    for (int s = 64; s > 0; s >>= 1) {
        if (tid < s) red[tid] = fmaxf(red[tid], red[tid + s]);
        __syncthreads();
    }
    float mx = red[0]; __syncthreads();

    // exp + sum
    float ls = 0.f;
    for (int j = tid; j < Lq; j += 128) {
        float e = expf(sc[j] - mx);
        sc[j] = e;
        ls += e;
    }
    red[tid] = ls; __syncthreads();
    for (int s = 64; s > 0; s >>= 1) {
        if (tid < s) red[tid] += red[tid + s];
        __syncthreads();
    }
    float inv = 1.0f / red[0]; __syncthreads();

    // o = attn @ v  (threads 0..63 each own one head dim; coalesced v reads)
    if (tid < DK_) {
        float acc = 0.f;
        const float* vbase = v + ((size_t)(b * S_) * D_ + h * DK_ + tid);
        for (int j = 0; j < Lq; j++)
            acc += sc[j] * vbase[(size_t)j * D_];
        o[(size_t)(b * S_ + qi) * D_ + h * DK_ + tid] = acc * inv;
    }
}

// ---------------- host orchestration ----------------
static inline dim3 gemm_grid(int M, int N) {
    return dim3((N + BN - 1) / BN, (M + BM - 1) / BM);
}

extern "C" void kernel_launch(void* const* d_in, const int* in_sizes, int n_in,
                              void* d_out, int out_size) {
    const int*   ids   = (const int*)  d_in[0];
    const float* tok   = (const float*)d_in[1];
    const float* pos   = (const float*)d_in[2];
    const float* wq    = (const float*)d_in[3];
    const float* bq    = (const float*)d_in[4];
    const float* wk    = (const float*)d_in[5];
    const float* bk    = (const float*)d_in[6];
    const float* wv    = (const float*)d_in[7];
    const float* bv    = (const float*)d_in[8];
    const float* wo    = (const float*)d_in[9];
    const float* bo    = (const float*)d_in[10];
    const float* w1    = (const float*)d_in[11];
    const float* b1    = (const float*)d_in[12];
    const float* w2    = (const float*)d_in[13];
    const float* b2    = (const float*)d_in[14];
    const float* ln1g  = (const float*)d_in[15];
    const float* ln1b  = (const float*)d_in[16];
    const float* ln2g  = (const float*)d_in[17];
    const float* ln2b  = (const float*)d_in[18];
    const float* lnfg  = (const float*)d_in[19];
    const float* lnfb  = (const float*)d_in[20];
    float* out = (float*)d_out;

    float *x, *h, *q, *k, *v, *att, *ff;
    cudaGetSymbolAddress((void**)&x,   g_x);
    cudaGetSymbolAddress((void**)&h,   g_h);
    cudaGetSymbolAddress((void**)&q,   g_q);
    cudaGetSymbolAddress((void**)&k,   g_k);
    cudaGetSymbolAddress((void**)&v,   g_v);
    cudaGetSymbolAddress((void**)&att, g_att);
    cudaGetSymbolAddress((void**)&ff,  g_ff);

    // embedding
    embed_kernel<<<M_, 256>>>(ids, tok, pos, x);

    for (int l = 0; l < L_; l++) {
        const float* wq_ = wq + (size_t)l * D_ * D_;
        const float* wk_ = wk + (size_t)l * D_ * D_;
        const float* wv_ = wv + (size_t)l * D_ * D_;
        const float* wo_ = wo + (size_t)l * D_ * D_;
        const float* w1_ = w1 + (size_t)l * D_ * DF_;
        const float* w2_ = w2 + (size_t)l * DF_ * D_;

        // LN1
        ln_kernel<<<M_, 256>>>(x, ln1g + l * D_, ln1b + l * D_, h);

        // QKV projections
        sgemm_kernel<EPI_NONE, false><<<gemm_grid(M_, D_), 256>>>(
            h, wq_, bq + l * D_, nullptr, q, M_, D_, D_);
        sgemm_kernel<EPI_NONE, false><<<gemm_grid(M_, D_), 256>>>(
            h, wk_, bk + l * D_, nullptr, k, M_, D_, D_);
        sgemm_kernel<EPI_NONE, false><<<gemm_grid(M_, D_), 256>>>(
            h, wv_, bv + l * D_, nullptr, v, M_, D_, D_);

        // attention
        attn_kernel<<<dim3(S_, H_, B_), 128>>>(q, k, v, att);

        // output projection + residual
        sgemm_kernel<EPI_RESID, false><<<gemm_grid(M_, D_), 256>>>(
            att, wo_, bo + l * D_, x, x, M_, D_, D_);

        // LN2
        ln_kernel<<<M_, 256>>>(x, ln2g + l * D_, ln2b + l * D_, h);

        // MLP
        sgemm_kernel<EPI_GELU, false><<<gemm_grid(M_, DF_), 256>>>(
            h, w1_, b1 + l * DF_, nullptr, ff, M_, DF_, D_);
        sgemm_kernel<EPI_RESID, false><<<gemm_grid(M_, D_), 256>>>(
            ff, w2_, b2 + l * D_, x, x, M_, D_, DF_);
    }

    // final LN + tied lm_head: logits = h @ tok_emb^T
    ln_kernel<<<M_, 256>>>(x, lnfg, lnfb, h);
    sgemm_kernel<EPI_NONE, true><<<gemm_grid(M_, V_), 256>>>(
        h, tok, nullptr, nullptr, out, M_, V_, D_);
}

// round 3
// speedup vs baseline: 1.3073x; 1.3073x over previous
#include <cuda_runtime.h>
#include <cuda_bf16.h>
#include <stdint.h>
#include <math.h>

// ---------------- problem constants ----------------
#define B_   2
#define S_   512
#define M_   (B_ * S_)      // 1024 rows
#define D_   768
#define H_   12
#define DK_  64
#define DF_  3072
#define L_   12
#define V_   50257
#define EPS_ 1e-5f

// ---------------- scratch ----------------
__device__ float g_x  [M_ * D_];
__device__ float g_h  [M_ * D_];
__device__ float g_q  [M_ * D_];
__device__ float g_k  [M_ * D_];
__device__ float g_v  [M_ * D_];
__device__ float g_att[M_ * D_];
__device__ float g_ff [M_ * DF_];

// ---------------- embedding ----------------
__global__ void embed_kernel(const int* __restrict__ ids,
                             const float* __restrict__ tok,
                             const float* __restrict__ pos,
                             float* __restrict__ x) {
    int r = blockIdx.x;
    int s = r % S_;
    int id = ids[r];
    const float* t = tok + (size_t)id * D_;
    const float* p = pos + (size_t)s  * D_;
    float* xr = x + (size_t)r * D_;
    for (int d = threadIdx.x; d < D_; d += blockDim.x)
        xr[d] = t[d] + p[d];
}

// ---------------- layernorm ----------------
__global__ void ln_kernel(const float* __restrict__ x,
                          const float* __restrict__ g,
                          const float* __restrict__ b,
                          float* __restrict__ y) {
    __shared__ float red[256];
    int r = blockIdx.x;
    int tid = threadIdx.x;
    const float* xr = x + (size_t)r * D_;
    float* yr = y + (size_t)r * D_;

    float s = 0.f;
    for (int d = tid; d < D_; d += 256) s += xr[d];
    red[tid] = s; __syncthreads();
    for (int k = 128; k > 0; k >>= 1) {
        if (tid < k) red[tid] += red[tid + k];
        __syncthreads();
    }
    float mean = red[0] * (1.0f / D_);
    __syncthreads();

    float v = 0.f;
    for (int d = tid; d < D_; d += 256) { float t = xr[d] - mean; v += t * t; }
    red[tid] = v; __syncthreads();
    for (int k = 128; k > 0; k >>= 1) {
        if (tid < k) red[tid] += red[tid + k];
        __syncthreads();
    }
    float inv = rsqrtf(red[0] * (1.0f / D_) + EPS_);

    for (int d = tid; d < D_; d += 256)
        yr[d] = (xr[d] - mean) * inv * g[d] + b[d];
}

// ---------------- tf32x3 tensor-core GEMM ----------------
// C[M,N] = A[M,K] @ B (+bias) (+resid | gelu), fp32 in/out, ~fp32 accuracy.
// TRANSB=false: B is [K,N] row-major. TRANSB=true: B is [N,K] row-major.
#define BM 128
#define BN 64
#define BK 16

enum { EPI_NONE = 0, EPI_RESID = 1, EPI_GELU = 2 };

struct GemmPtrs {
    const float* Bw;
    const float* bias;
    const float* resid;
    float*       C;
};

__device__ __forceinline__ uint32_t f2tf(float x) {
    uint32_t r;
    asm("cvt.rna.tf32.f32 %0, %1;" : "=r"(r) : "f"(x));
    return r;
}

__device__ __forceinline__ void mma_tf32(float c[4], const uint32_t a[4], const uint32_t b[2]) {
    asm volatile("mma.sync.aligned.m16n8k8.row.col.f32.tf32.tf32.f32 "
                 "{%0,%1,%2,%3}, {%4,%5,%6,%7}, {%8,%9}, {%0,%1,%2,%3};"
                 : "+f"(c[0]), "+f"(c[1]), "+f"(c[2]), "+f"(c[3])
                 : "r"(a[0]), "r"(a[1]), "r"(a[2]), "r"(a[3]),
                   "r"(b[0]), "r"(b[1]));
}

// XOR swizzle: conflict-free fragment loads
__device__ __forceinline__ int swA(int k, int m) { return k * BM + (m ^ ((k & 3) << 3)); }
__device__ __forceinline__ int swB(int k, int n) { return k * BN + (n ^ ((k & 3) << 3)); }

template<int EPI, bool TRANSB>
__global__ __launch_bounds__(256, 2)
void tf32_gemm(const float* __restrict__ A,
               GemmPtrs p0, GemmPtrs p1, GemmPtrs p2,
               int M, int N, int K) {
    GemmPtrs p = (blockIdx.z == 0) ? p0 : ((blockIdx.z == 1) ? p1 : p2);

    __shared__ uint32_t sAh[BK * BM];
    __shared__ uint32_t sAl[BK * BM];
    __shared__ uint32_t sBh[BK * BN];
    __shared__ uint32_t sBl[BK * BN];

    int tid  = threadIdx.x;
    int lane = tid & 31;
    int warp = tid >> 5;
    int gid  = lane >> 2;      // 0..7
    int tig  = lane & 3;       // 0..3
    int wm   = (warp >> 1) * 32;   // 0,32,64,96
    int wn   = (warp & 1) * 32;    // 0,32
    int m0   = blockIdx.y * BM;
    int n0   = blockIdx.x * BN;

    float acc[2][4][4] = {};

    // register staging for global->smem
    float aReg[8];   // 128x16 / 256 thr
    float bReg[4];   // 16x64  / 256 thr

    const int nIt = K / BK;

    // ---- prologue: load tile 0 ----
    {
        #pragma unroll
        for (int i = 0; i < 8; i++) {
            int idx = tid + i * 256;
            int k = idx & 15, m = idx >> 4;
            aReg[i] = A[(size_t)(m0 + m) * K + k];
        }
        #pragma unroll
        for (int i = 0; i < 4; i++) {
            int idx = tid + i * 256;
            int k, n;
            if (!TRANSB) { n = idx & 63; k = idx >> 6; }
            else         { k = idx & 15; n = idx >> 4; }
            int gn = n0 + n;
            if (!TRANSB) bReg[i] = (gn < N) ? p.Bw[(size_t)k * N + gn] : 0.f;
            else         bReg[i] = (gn < N) ? p.Bw[(size_t)gn * K + k] : 0.f;
        }
    }

    for (int it = 0; it < nIt; ++it) {
        __syncthreads();
        // ---- store staged regs (split into tf32 hi/lo) ----
        #pragma unroll
        for (int i = 0; i < 8; i++) {
            int idx = tid + i * 256;
            int k = idx & 15, m = idx >> 4;
            uint32_t hi = f2tf(aReg[i]);
            float lo = aReg[i] - __uint_as_float(hi);
            sAh[swA(k, m)] = hi;
            sAl[swA(k, m)] = f2tf(lo);
        }
        #pragma unroll
        for (int i = 0; i < 4; i++) {
            int idx = tid + i * 256;
            int k, n;
            if (!TRANSB) { n = idx & 63; k = idx >> 6; }
            else         { k = idx & 15; n = idx >> 4; }
            uint32_t hi = f2tf(bReg[i]);
            float lo = bReg[i] - __uint_as_float(hi);
            sBh[swB(k, n)] = hi;
            sBl[swB(k, n)] = f2tf(lo);
        }
        __syncthreads();

        // ---- prefetch next tile into regs (overlaps compute) ----
        if (it + 1 < nIt) {
            int k0 = (it + 1) * BK;
            #pragma unroll
            for (int i = 0; i < 8; i++) {
                int idx = tid + i * 256;
                int k = idx & 15, m = idx >> 4;
                aReg[i] = A[(size_t)(m0 + m) * K + (k0 + k)];
            }
            #pragma unroll
            for (int i = 0; i < 4; i++) {
                int idx = tid + i * 256;
                int k, n;
                if (!TRANSB) { n = idx & 63; k = idx >> 6; }
                else         { k = idx & 15; n = idx >> 4; }
                int gn = n0 + n;
                if (!TRANSB) bReg[i] = (gn < N) ? p.Bw[(size_t)(k0 + k) * N + gn] : 0.f;
                else         bReg[i] = (gn < N) ? p.Bw[(size_t)gn * K + (k0 + k)] : 0.f;
            }
        }

        // ---- compute: 2 x k8 steps ----
        #pragma unroll
        for (int ks = 0; ks < BK; ks += 8) {
            uint32_t bh[4][2], bl[4][2];
            #pragma unroll
            for (int nt = 0; nt < 4; nt++) {
                int n = wn + nt * 8 + gid;
                bh[nt][0] = sBh[swB(ks + tig,     n)];
                bh[nt][1] = sBh[swB(ks + tig + 4, n)];
                bl[nt][0] = sBl[swB(ks + tig,     n)];
                bl[nt][1] = sBl[swB(ks + tig + 4, n)];
            }
            #pragma unroll
            for (int mt = 0; mt < 2; mt++) {
                int mb = wm + mt * 16;
                uint32_t ah[4], al[4];
                ah[0] = sAh[swA(ks + tig,     mb + gid)];
                ah[1] = sAh[swA(ks + tig,     mb + gid + 8)];
                ah[2] = sAh[swA(ks + tig + 4, mb + gid)];
                ah[3] = sAh[swA(ks + tig + 4, mb + gid + 8)];
                al[0] = sAl[swA(ks + tig,     mb + gid)];
                al[1] = sAl[swA(ks + tig,     mb + gid + 8)];
                al[2] = sAl[swA(ks + tig + 4, mb + gid)];
                al[3] = sAl[swA(ks + tig + 4, mb + gid + 8)];
                #pragma unroll
                for (int nt = 0; nt < 4; nt++) {
                    mma_tf32(acc[mt][nt], ah, bh[nt]);  // hi*hi
                    mma_tf32(acc[mt][nt], ah, bl[nt]);  // hi*lo
                    mma_tf32(acc[mt][nt], al, bh[nt]);  // lo*hi
                }
            }
        }
    }

    // ---- epilogue ----
    #pragma unroll
    for (int mt = 0; mt < 2; mt++) {
        int r0 = m0 + wm + mt * 16 + gid;
        #pragma unroll
        for (int nt = 0; nt < 4; nt++) {
            int cn = n0 + wn + nt * 8 + tig * 2;
            #pragma unroll
            for (int e = 0; e < 4; e++) {
                int gm = r0 + (e >> 1) * 8;           // c0,c1 row; c2,c3 row+8
                int gn = cn + (e & 1);
                if (gn >= N) continue;
                float c = acc[mt][nt][e];
                if (p.bias) c += p.bias[gn];
                if (EPI == EPI_RESID) c += p.resid[(size_t)gm * N + gn];
                if (EPI == EPI_GELU)  c = 0.5f * c * (1.0f + erff(c * 0.70710678118654752f));
                p.C[(size_t)gm * N + gn] = c;
            }
        }
    }
}

// ---------------- causal attention ----------------
__global__ void attn_kernel(const float* __restrict__ q,
                            const float* __restrict__ k,
                            const float* __restrict__ v,
                            float* __restrict__ o) {
    int qi = blockIdx.x;
    int h  = blockIdx.y;
    int b  = blockIdx.z;
    int tid = threadIdx.x;                    // 128 threads

    __shared__ float qs[DK_];
    __shared__ float sc[S_];
    __shared__ float red[128];

    const float* qrow = q + ((size_t)(b * S_ + qi) * D_ + h * DK_);
    if (tid < DK_) qs[tid] = qrow[tid];
    __syncthreads();

    int Lq = qi + 1;

    for (int j = tid; j < Lq; j += 128) {
        const float* krow = k + ((size_t)(b * S_ + j) * D_ + h * DK_);
        float s = 0.f;
        #pragma unroll
        for (int d = 0; d < DK_; d++) s += qs[d] * krow[d];
        sc[j] = s * 0.125f;
    }
    __syncthreads();

    float lm = -1e30f;
    for (int j = tid; j < Lq; j += 128) lm = fmaxf(lm, sc[j]);
    red[tid] = lm; __syncthreads();
    for (int s = 64; s > 0; s >>= 1) {
        if (tid < s) red[tid] = fmaxf(red[tid], red[tid + s]);
        __syncthreads();
    }
    float mx = red[0]; __syncthreads();

    float ls = 0.f;
    for (int j = tid; j < Lq; j += 128) {
        float e = expf(sc[j] - mx);
        sc[j] = e;
        ls += e;
    }
    red[tid] = ls; __syncthreads();
    for (int s = 64; s > 0; s >>= 1) {
        if (tid < s) red[tid] += red[tid + s];
        __syncthreads();
    }
    float inv = 1.0f / red[0]; __syncthreads();

    // o = attn @ v : split j-range across two halves of the block
    int d    = tid & 63;
    int half = tid >> 6;
    float acc = 0.f;
    const float* vbase = v + ((size_t)(b * S_) * D_ + h * DK_ + d);
    for (int j = half; j < Lq; j += 2)
        acc += sc[j] * vbase[(size_t)j * D_];
    red[tid] = acc;
    __syncthreads();
    if (tid < 64)
        o[(size_t)(b * S_ + qi) * D_ + h * DK_ + d] = (red[tid] + red[tid + 64]) * inv;
}

// ---------------- host orchestration ----------------
static inline dim3 gemm_grid(int M, int N, int z) {
    return dim3((N + BN - 1) / BN, (M + BM - 1) / BM, z);
}

extern "C" void kernel_launch(void* const* d_in, const int* in_sizes, int n_in,
                              void* d_out, int out_size) {
    const int*   ids   = (const int*)  d_in[0];
    const float* tok   = (const float*)d_in[1];
    const float* pos   = (const float*)d_in[2];
    const float* wq    = (const float*)d_in[3];
    const float* bq    = (const float*)d_in[4];
    const float* wk    = (const float*)d_in[5];
    const float* bk    = (const float*)d_in[6];
    const float* wv    = (const float*)d_in[7];
    const float* bv    = (const float*)d_in[8];
    const float* wo    = (const float*)d_in[9];
    const float* bo    = (const float*)d_in[10];
    const float* w1    = (const float*)d_in[11];
    const float* b1    = (const float*)d_in[12];
    const float* w2    = (const float*)d_in[13];
    const float* b2    = (const float*)d_in[14];
    const float* ln1g  = (const float*)d_in[15];
    const float* ln1b  = (const float*)d_in[16];
    const float* ln2g  = (const float*)d_in[17];
    const float* ln2b  = (const float*)d_in[18];
    const float* lnfg  = (const float*)d_in[19];
    const float* lnfb  = (const float*)d_in[20];
    float* out = (float*)d_out;

    float *x, *h, *q, *k, *v, *att, *ff;
    cudaGetSymbolAddress((void**)&x,   g_x);
    cudaGetSymbolAddress((void**)&h,   g_h);
    cudaGetSymbolAddress((void**)&q,   g_q);
    cudaGetSymbolAddress((void**)&k,   g_k);
    cudaGetSymbolAddress((void**)&v,   g_v);
    cudaGetSymbolAddress((void**)&att, g_att);
    cudaGetSymbolAddress((void**)&ff,  g_ff);

    embed_kernel<<<M_, 256>>>(ids, tok, pos, x);

    for (int l = 0; l < L_; l++) {
        const float* wq_ = wq + (size_t)l * D_ * D_;
        const float* wk_ = wk + (size_t)l * D_ * D_;
        const float* wv_ = wv + (size_t)l * D_ * D_;
        const float* wo_ = wo + (size_t)l * D_ * D_;
        const float* w1_ = w1 + (size_t)l * D_ * DF_;
        const float* w2_ = w2 + (size_t)l * DF_ * D_;

        ln_kernel<<<M_, 256>>>(x, ln1g + l * D_, ln1b + l * D_, h);

        // fused QKV: one launch, blockIdx.z selects matrix
        {
            GemmPtrs pq = { wq_, bq + l * D_, nullptr, q };
            GemmPtrs pk = { wk_, bk + l * D_, nullptr, k };
            GemmPtrs pv = { wv_, bv + l * D_, nullptr, v };
            tf32_gemm<EPI_NONE, false><<<gemm_grid(M_, D_, 3), 256>>>(
                h, pq, pk, pv, M_, D_, D_);
        }

        attn_kernel<<<dim3(S_, H_, B_), 128>>>(q, k, v, att);

        {
            GemmPtrs po = { wo_, bo + l * D_, x, x };
            tf32_gemm<EPI_RESID, false><<<gemm_grid(M_, D_, 1), 256>>>(
                att, po, po, po, M_, D_, D_);
        }

        ln_kernel<<<M_, 256>>>(x, ln2g + l * D_, ln2b + l * D_, h);

        {
            GemmPtrs p1_ = { w1_, b1 + l * DF_, nullptr, ff };
            tf32_gemm<EPI_GELU, false><<<gemm_grid(M_, DF_, 1), 256>>>(
                h, p1_, p1_, p1_, M_, DF_, D_);
        }
        {
            GemmPtrs p2_ = { w2_, b2 + l * D_, x, x };
            tf32_gemm<EPI_RESID, false><<<gemm_grid(M_, D_, 1), 256>>>(
                ff, p2_, p2_, p2_, M_, D_, DF_);
        }
    }

    ln_kernel<<<M_, 256>>>(x, lnfg, lnfb, h);
    {
        GemmPtrs pl = { tok, nullptr, nullptr, out };
        tf32_gemm<EPI_NONE, true><<<gemm_grid(M_, V_, 1), 256>>>(
            h, pl, pl, pl, M_, V_, D_);
    }
}

// round 4
// speedup vs baseline: 2.4032x; 1.8383x over previous
#include <cuda_runtime.h>
#include <cuda_bf16.h>
#include <stdint.h>
#include <math.h>

// ---------------- problem constants ----------------
#define B_   2
#define S_   512
#define M_   (B_ * S_)      // 1024 rows
#define D_   768
#define H_   12
#define DK_  64
#define DF_  3072
#define L_   12
#define V_   50257
#define EPS_ 1e-5f

// ---------------- scratch ----------------
__device__ float g_x  [M_ * D_];
__device__ float g_h  [M_ * D_];
__device__ float g_q  [M_ * D_];
__device__ float g_k  [M_ * D_];
__device__ float g_v  [M_ * D_];
__device__ float g_att[M_ * D_];
__device__ float g_ff [M_ * DF_];

// ---------------- embedding ----------------
__global__ void embed_kernel(const int* __restrict__ ids,
                             const float* __restrict__ tok,
                             const float* __restrict__ pos,
                             float* __restrict__ x) {
    int r = blockIdx.x;
    int s = r % S_;
    int id = ids[r];
    const float* t = tok + (size_t)id * D_;
    const float* p = pos + (size_t)s  * D_;
    float* xr = x + (size_t)r * D_;
    for (int d = threadIdx.x; d < D_; d += blockDim.x)
        xr[d] = t[d] + p[d];
}

// ---------------- layernorm ----------------
__global__ void ln_kernel(const float* __restrict__ x,
                          const float* __restrict__ g,
                          const float* __restrict__ b,
                          float* __restrict__ y) {
    __shared__ float red[256];
    int r = blockIdx.x;
    int tid = threadIdx.x;
    const float* xr = x + (size_t)r * D_;
    float* yr = y + (size_t)r * D_;

    float s = 0.f;
    for (int d = tid; d < D_; d += 256) s += xr[d];
    red[tid] = s; __syncthreads();
    for (int k = 128; k > 0; k >>= 1) {
        if (tid < k) red[tid] += red[tid + k];
        __syncthreads();
    }
    float mean = red[0] * (1.0f / D_);
    __syncthreads();

    float v = 0.f;
    for (int d = tid; d < D_; d += 256) { float t = xr[d] - mean; v += t * t; }
    red[tid] = v; __syncthreads();
    for (int k = 128; k > 0; k >>= 1) {
        if (tid < k) red[tid] += red[tid + k];
        __syncthreads();
    }
    float inv = rsqrtf(red[0] * (1.0f / D_) + EPS_);

    for (int d = tid; d < D_; d += 256)
        yr[d] = (xr[d] - mean) * inv * g[d] + b[d];
}

// ---------------- tf32x3 tensor-core GEMM ----------------
#define BM 128
#define BN 64
#define BK 16

enum { EPI_NONE = 0, EPI_RESID = 1, EPI_GELU = 2 };

struct GemmPtrs {
    const float* Bw;
    const float* bias;
    const float* resid;
    float*       C;
};

__device__ __forceinline__ uint32_t f2tf(float x) {
    uint32_t r;
    asm("cvt.rna.tf32.f32 %0, %1;" : "=r"(r) : "f"(x));
    return r;
}

__device__ __forceinline__ void mma_tf32(float c[4], const uint32_t a[4], const uint32_t b[2]) {
    asm volatile("mma.sync.aligned.m16n8k8.row.col.f32.tf32.tf32.f32 "
                 "{%0,%1,%2,%3}, {%4,%5,%6,%7}, {%8,%9}, {%0,%1,%2,%3};"
                 : "+f"(c[0]), "+f"(c[1]), "+f"(c[2]), "+f"(c[3])
                 : "r"(a[0]), "r"(a[1]), "r"(a[2]), "r"(a[3]),
                   "r"(b[0]), "r"(b[1]));
}

__device__ __forceinline__ int swA(int k, int m) { return k * BM + (m ^ ((k & 3) << 3)); }
__device__ __forceinline__ int swB(int k, int n) { return k * BN + (n ^ ((k & 3) << 3)); }

template<int EPI, bool TRANSB>
__global__ __launch_bounds__(256, 2)
void tf32_gemm(const float* __restrict__ A,
               GemmPtrs p0, GemmPtrs p1, GemmPtrs p2,
               int M, int N, int K) {
    GemmPtrs p = (blockIdx.z == 0) ? p0 : ((blockIdx.z == 1) ? p1 : p2);

    __shared__ uint32_t sAh[BK * BM];
    __shared__ uint32_t sAl[BK * BM];
    __shared__ uint32_t sBh[BK * BN];
    __shared__ uint32_t sBl[BK * BN];

    int tid  = threadIdx.x;
    int lane = tid & 31;
    int warp = tid >> 5;
    int gid  = lane >> 2;
    int tig  = lane & 3;
    int wm   = (warp >> 1) * 32;
    int wn   = (warp & 1) * 32;
    int m0   = blockIdx.y * BM;
    int n0   = blockIdx.x * BN;

    float acc[2][4][4] = {};

    float aReg[8];
    float bReg[4];

    const int nIt = K / BK;

    {
        #pragma unroll
        for (int i = 0; i < 8; i++) {
            int idx = tid + i * 256;
            int k = idx & 15, m = idx >> 4;
            aReg[i] = A[(size_t)(m0 + m) * K + k];
        }
        #pragma unroll
        for (int i = 0; i < 4; i++) {
            int idx = tid + i * 256;
            int k, n;
            if (!TRANSB) { n = idx & 63; k = idx >> 6; }
            else         { k = idx & 15; n = idx >> 4; }
            int gn = n0 + n;
            if (!TRANSB) bReg[i] = (gn < N) ? p.Bw[(size_t)k * N + gn] : 0.f;
            else         bReg[i] = (gn < N) ? p.Bw[(size_t)gn * K + k] : 0.f;
        }
    }

    for (int it = 0; it < nIt; ++it) {
        __syncthreads();
        #pragma unroll
        for (int i = 0; i < 8; i++) {
            int idx = tid + i * 256;
            int k = idx & 15, m = idx >> 4;
            uint32_t hi = f2tf(aReg[i]);
            float lo = aReg[i] - __uint_as_float(hi);
            sAh[swA(k, m)] = hi;
            sAl[swA(k, m)] = f2tf(lo);
        }
        #pragma unroll
        for (int i = 0; i < 4; i++) {
            int idx = tid + i * 256;
            int k, n;
            if (!TRANSB) { n = idx & 63; k = idx >> 6; }
            else         { k = idx & 15; n = idx >> 4; }
            uint32_t hi = f2tf(bReg[i]);
            float lo = bReg[i] - __uint_as_float(hi);
            sBh[swB(k, n)] = hi;
            sBl[swB(k, n)] = f2tf(lo);
        }
        __syncthreads();

        if (it + 1 < nIt) {
            int k0 = (it + 1) * BK;
            #pragma unroll
            for (int i = 0; i < 8; i++) {
                int idx = tid + i * 256;
                int k = idx & 15, m = idx >> 4;
                aReg[i] = A[(size_t)(m0 + m) * K + (k0 + k)];
            }
            #pragma unroll
            for (int i = 0; i < 4; i++) {
                int idx = tid + i * 256;
                int k, n;
                if (!TRANSB) { n = idx & 63; k = idx >> 6; }
                else         { k = idx & 15; n = idx >> 4; }
                int gn = n0 + n;
                if (!TRANSB) bReg[i] = (gn < N) ? p.Bw[(size_t)(k0 + k) * N + gn] : 0.f;
                else         bReg[i] = (gn < N) ? p.Bw[(size_t)gn * K + (k0 + k)] : 0.f;
            }
        }

        #pragma unroll
        for (int ks = 0; ks < BK; ks += 8) {
            uint32_t bh[4][2], bl[4][2];
            #pragma unroll
            for (int nt = 0; nt < 4; nt++) {
                int n = wn + nt * 8 + gid;
                bh[nt][0] = sBh[swB(ks + tig,     n)];
                bh[nt][1] = sBh[swB(ks + tig + 4, n)];
                bl[nt][0] = sBl[swB(ks + tig,     n)];
                bl[nt][1] = sBl[swB(ks + tig + 4, n)];
            }
            #pragma unroll
            for (int mt = 0; mt < 2; mt++) {
                int mb = wm + mt * 16;
                uint32_t ah[4], al[4];
                ah[0] = sAh[swA(ks + tig,     mb + gid)];
                ah[1] = sAh[swA(ks + tig,     mb + gid + 8)];
                ah[2] = sAh[swA(ks + tig + 4, mb + gid)];
                ah[3] = sAh[swA(ks + tig + 4, mb + gid + 8)];
                al[0] = sAl[swA(ks + tig,     mb + gid)];
                al[1] = sAl[swA(ks + tig,     mb + gid + 8)];
                al[2] = sAl[swA(ks + tig + 4, mb + gid)];
                al[3] = sAl[swA(ks + tig + 4, mb + gid + 8)];
                #pragma unroll
                for (int nt = 0; nt < 4; nt++) {
                    mma_tf32(acc[mt][nt], ah, bh[nt]);
                    mma_tf32(acc[mt][nt], ah, bl[nt]);
                    mma_tf32(acc[mt][nt], al, bh[nt]);
                }
            }
        }
    }

    #pragma unroll
    for (int mt = 0; mt < 2; mt++) {
        int r0 = m0 + wm + mt * 16 + gid;
        #pragma unroll
        for (int nt = 0; nt < 4; nt++) {
            int cn = n0 + wn + nt * 8 + tig * 2;
            #pragma unroll
            for (int e = 0; e < 4; e++) {
                int gm = r0 + (e >> 1) * 8;
                int gn = cn + (e & 1);
                if (gn >= N) continue;
                float c = acc[mt][nt][e];
                if (p.bias) c += p.bias[gn];
                if (EPI == EPI_RESID) c += p.resid[(size_t)gm * N + gn];
                if (EPI == EPI_GELU)  c = 0.5f * c * (1.0f + erff(c * 0.70710678118654752f));
                p.C[(size_t)gm * N + gn] = c;
            }
        }
    }
}

// ---------------- flash-style causal attention ----------------
// One block per (64-query tile, head, batch). 256 threads.
// Dynamic SMEM layout (floats):
//   sQ  [64][65]  (transposed: [d][q], pre-scaled by 1/8)   at 0
//   sKP [64][65]  (K as [d][j], then reused for P as [j][q]) at 4160
//   sV  [64][65]  ([j][d])                                   at 8320
//   salpha[64] at 12480, slinv[64] at 12544  -> total 12608 floats
#define ATTN_SMEM_FLOATS 12608

__global__ __launch_bounds__(256)
void attn_flash_kernel(const float* __restrict__ qg,
                       const float* __restrict__ kg,
                       const float* __restrict__ vg,
                       float* __restrict__ og) {
    extern __shared__ float sm[];
    float* sQ  = sm;
    float* sKP = sm + 4160;
    float* sV  = sm + 8320;
    float* salpha = sm + 12480;
    float* slinv  = sm + 12544;

    int qt = blockIdx.x;          // 0..7
    int h  = blockIdx.y;
    int b  = blockIdx.z;
    int tid = threadIdx.x;
    int tx = tid & 15;            // j / d micro
    int ty = tid >> 4;            // q micro
    int q0 = qt * 64;

    // load Q tile transposed + scaled
    #pragma unroll
    for (int i = 0; i < 16; i++) {
        int idx = tid + i * 256;
        int r = idx >> 6, d = idx & 63;
        sQ[d * 65 + r] = qg[(size_t)(b * S_ + q0 + r) * D_ + h * DK_ + d] * 0.125f;
    }

    float m_run = -1e30f, l_run = 0.f;
    float Oacc[4][4] = {};
    __syncthreads();

    for (int jt = 0; jt <= qt; jt++) {
        int j0 = jt * 64;
        // load K (transposed [d][j]) and V ([j][d])
        #pragma unroll
        for (int i = 0; i < 16; i++) {
            int idx = tid + i * 256;
            int r = idx >> 6, d = idx & 63;
            float kvK = kg[(size_t)(b * S_ + j0 + r) * D_ + h * DK_ + d];
            float kvV = vg[(size_t)(b * S_ + j0 + r) * D_ + h * DK_ + d];
            sKP[d * 65 + r] = kvK;
            sV [r * 65 + d] = kvV;
        }
        __syncthreads();

        // scores: S[q][j] = sum_d Q[q][d]*K[j][d]
        float s[4][4] = {};
        #pragma unroll
        for (int kk = 0; kk < 64; kk++) {
            float a[4], bb[4];
            #pragma unroll
            for (int i = 0; i < 4; i++) a[i]  = sQ [kk * 65 + ty * 4 + i];
            #pragma unroll
            for (int j = 0; j < 4; j++) bb[j] = sKP[kk * 65 + tx * 4 + j];
            #pragma unroll
            for (int i = 0; i < 4; i++)
                #pragma unroll
                for (int j = 0; j < 4; j++)
                    s[i][j] += a[i] * bb[j];
        }
        __syncthreads();   // all reads of sKP(K) done

        // write P (masked) into sKP as [j][q]
        bool diag = (jt == qt);
        #pragma unroll
        for (int i = 0; i < 4; i++)
            #pragma unroll
            for (int j = 0; j < 4; j++) {
                float val = s[i][j];
                if (diag && (tx * 4 + j) > (ty * 4 + i)) val = -1e30f;
                sKP[(tx * 4 + j) * 65 + (ty * 4 + i)] = val;
            }
        __syncthreads();

        // online softmax per q-row (threads 0..63)
        if (tid < 64) {
            int qr = tid;
            float mt = -1e30f;
            #pragma unroll 4
            for (int j = 0; j < 64; j++) mt = fmaxf(mt, sKP[j * 65 + qr]);
            float m_new = fmaxf(m_run, mt);
            float alpha = __expf(m_run - m_new);
            float lsum = 0.f;
            #pragma unroll 4
            for (int j = 0; j < 64; j++) {
                float e = __expf(sKP[j * 65 + qr] - m_new);
                sKP[j * 65 + qr] = e;
                lsum += e;
            }
            l_run = l_run * alpha + lsum;
            m_run = m_new;
            salpha[qr] = alpha;
        }
        __syncthreads();

        // rescale Oacc and accumulate P @ V
        #pragma unroll
        for (int i = 0; i < 4; i++) {
            float al = salpha[ty * 4 + i];
            #pragma unroll
            for (int j = 0; j < 4; j++) Oacc[i][j] *= al;
        }
        #pragma unroll
        for (int kk = 0; kk < 64; kk++) {
            float a[4], bb[4];
            #pragma unroll
            for (int i = 0; i < 4; i++) a[i]  = sKP[kk * 65 + ty * 4 + i];
            #pragma unroll
            for (int j = 0; j < 4; j++) bb[j] = sV [kk * 65 + tx * 4 + j];
            #pragma unroll
            for (int i = 0; i < 4; i++)
                #pragma unroll
                for (int j = 0; j < 4; j++)
                    Oacc[i][j] += a[i] * bb[j];
        }
        __syncthreads();   // before next tile overwrites buffers
    }

    if (tid < 64) slinv[tid] = 1.0f / l_run;
    __syncthreads();

    #pragma unroll
    for (int i = 0; i < 4; i++) {
        int qr = ty * 4 + i;
        float inv = slinv[qr];
        float4 val;
        val.x = Oacc[i][0] * inv;
        val.y = Oacc[i][1] * inv;
        val.z = Oacc[i][2] * inv;
        val.w = Oacc[i][3] * inv;
        *(float4*)&og[(size_t)(b * S_ + q0 + qr) * D_ + h * DK_ + tx * 4] = val;
    }
}

// ---------------- host orchestration ----------------
static inline dim3 gemm_grid(int M, int N, int z) {
    return dim3((N + BN - 1) / BN, (M + BM - 1) / BM, z);
}

extern "C" void kernel_launch(void* const* d_in, const int* in_sizes, int n_in,
                              void* d_out, int out_size) {
    const int*   ids   = (const int*)  d_in[0];
    const float* tok   = (const float*)d_in[1];
    const float* pos   = (const float*)d_in[2];
    const float* wq    = (const float*)d_in[3];
    const float* bq    = (const float*)d_in[4];
    const float* wk    = (const float*)d_in[5];
    const float* bk    = (const float*)d_in[6];
    const float* wv    = (const float*)d_in[7];
    const float* bv    = (const float*)d_in[8];
    const float* wo    = (const float*)d_in[9];
    const float* bo    = (const float*)d_in[10];
    const float* w1    = (const float*)d_in[11];
    const float* b1    = (const float*)d_in[12];
    const float* w2    = (const float*)d_in[13];
    const float* b2    = (const float*)d_in[14];
    const float* ln1g  = (const float*)d_in[15];
    const float* ln1b  = (const float*)d_in[16];
    const float* ln2g  = (const float*)d_in[17];
    const float* ln2b  = (const float*)d_in[18];
    const float* lnfg  = (const float*)d_in[19];
    const float* lnfb  = (const float*)d_in[20];
    float* out = (float*)d_out;

    float *x, *h, *q, *k, *v, *att, *ff;
    cudaGetSymbolAddress((void**)&x,   g_x);
    cudaGetSymbolAddress((void**)&h,   g_h);
    cudaGetSymbolAddress((void**)&q,   g_q);
    cudaGetSymbolAddress((void**)&k,   g_k);
    cudaGetSymbolAddress((void**)&v,   g_v);
    cudaGetSymbolAddress((void**)&att, g_att);
    cudaGetSymbolAddress((void**)&ff,  g_ff);

    const int attnSmem = ATTN_SMEM_FLOATS * sizeof(float);  // ~50.4 KB
    cudaFuncSetAttribute(attn_flash_kernel,
                         cudaFuncAttributeMaxDynamicSharedMemorySize, attnSmem);

    embed_kernel<<<M_, 256>>>(ids, tok, pos, x);

    for (int l = 0; l < L_; l++) {
        const float* wq_ = wq + (size_t)l * D_ * D_;
        const float* wk_ = wk + (size_t)l * D_ * D_;
        const float* wv_ = wv + (size_t)l * D_ * D_;
        const float* wo_ = wo + (size_t)l * D_ * D_;
        const float* w1_ = w1 + (size_t)l * D_ * DF_;
        const float* w2_ = w2 + (size_t)l * DF_ * D_;

        ln_kernel<<<M_, 256>>>(x, ln1g + l * D_, ln1b + l * D_, h);

        {
            GemmPtrs pq = { wq_, bq + l * D_, nullptr, q };
            GemmPtrs pk = { wk_, bk + l * D_, nullptr, k };
            GemmPtrs pv = { wv_, bv + l * D_, nullptr, v };
            tf32_gemm<EPI_NONE, false><<<gemm_grid(M_, D_, 3), 256>>>(
                h, pq, pk, pv, M_, D_, D_);
        }

        attn_flash_kernel<<<dim3(8, H_, B_), 256, attnSmem>>>(q, k, v, att);

        {
            GemmPtrs po = { wo_, bo + l * D_, x, x };
            tf32_gemm<EPI_RESID, false><<<gemm_grid(M_, D_, 1), 256>>>(
                att, po, po, po, M_, D_, D_);
        }

        ln_kernel<<<M_, 256>>>(x, ln2g + l * D_, ln2b + l * D_, h);

        {
            GemmPtrs p1_ = { w1_, b1 + l * DF_, nullptr, ff };
            tf32_gemm<EPI_GELU, false><<<gemm_grid(M_, DF_, 1), 256>>>(
                h, p1_, p1_, p1_, M_, DF_, D_);
        }
        {
            GemmPtrs p2_ = { w2_, b2 + l * D_, x, x };
            tf32_gemm<EPI_RESID, false><<<gemm_grid(M_, D_, 1), 256>>>(
                ff, p2_, p2_, p2_, M_, D_, DF_);
        }
    }

    ln_kernel<<<M_, 256>>>(x, lnfg, lnfb, h);
    {
        GemmPtrs pl = { tok, nullptr, nullptr, out };
        tf32_gemm<EPI_NONE, true><<<gemm_grid(M_, V_, 1), 256>>>(
            h, pl, pl, pl, M_, V_, D_);
    }
}

// round 5
// speedup vs baseline: 4.8953x; 2.0370x over previous
#include <cuda_runtime.h>
#include <cuda_bf16.h>
#include <stdint.h>
#include <math.h>

// ---------------- problem constants ----------------
#define B_    2
#define S_    512
#define M_    1024
#define D_    768
#define H_    12
#define DK_   64
#define DF_   3072
#define L_    12
#define V_    50257
#define QKVN  (3 * D_)     // 2304
#define EPS_  1e-5f

// ---------------- scratch (device globals) ----------------
__device__ float          g_x[M_ * D_];
__device__ __nv_bfloat16  g_h_hi[M_ * D_],  g_h_lo[M_ * D_];
__device__ float          g_qkv[M_ * QKVN];
__device__ __nv_bfloat16  g_att_hi[M_ * D_], g_att_lo[M_ * D_];
__device__ __nv_bfloat16  g_ff_hi[M_ * DF_], g_ff_lo[M_ * DF_];
// pre-split / pre-transposed weights, layout [L][N][K] bf16
__device__ __nv_bfloat16  g_wqkv_hi[L_ * QKVN * D_], g_wqkv_lo[L_ * QKVN * D_];
__device__ __nv_bfloat16  g_wo_hi[L_ * D_ * D_],     g_wo_lo[L_ * D_ * D_];
__device__ __nv_bfloat16  g_w1_hi[L_ * DF_ * D_],    g_w1_lo[L_ * DF_ * D_];
__device__ __nv_bfloat16  g_w2_hi[L_ * D_ * DF_],    g_w2_lo[L_ * D_ * DF_];
__device__ __nv_bfloat16  g_tok_hi[(size_t)V_ * D_], g_tok_lo[(size_t)V_ * D_];
__device__ float          g_bqkv[L_ * QKVN];

// ---------------- small helpers ----------------
__device__ __forceinline__ void split_bf16(float x, __nv_bfloat16& hi, __nv_bfloat16& lo) {
    hi = __float2bfloat16(x);
    lo = __float2bfloat16(x - __bfloat162float(hi));
}

__device__ __forceinline__ void cp16(uint32_t saddr, const void* g) {
    asm volatile("cp.async.cg.shared.global [%0], [%1], 16;\n" :: "r"(saddr), "l"(g));
}

__device__ __forceinline__ void ldm4(uint32_t a[4], uint32_t saddr) {
    asm volatile("ldmatrix.sync.aligned.m8n8.x4.shared.b16 {%0,%1,%2,%3}, [%4];"
                 : "=r"(a[0]), "=r"(a[1]), "=r"(a[2]), "=r"(a[3]) : "r"(saddr));
}

__device__ __forceinline__ void mma_bf16(float c[4], const uint32_t a[4], const uint32_t b[2]) {
    asm volatile("mma.sync.aligned.m16n8k16.row.col.f32.bf16.bf16.f32 "
                 "{%0,%1,%2,%3}, {%4,%5,%6,%7}, {%8,%9}, {%0,%1,%2,%3};"
                 : "+f"(c[0]), "+f"(c[1]), "+f"(c[2]), "+f"(c[3])
                 : "r"(a[0]), "r"(a[1]), "r"(a[2]), "r"(a[3]),
                   "r"(b[0]), "r"(b[1]));
}

// ---------------- prepass: split+transpose weights ----------------
// src: fp32 [K][N] per layer. dst: bf16 [N][K] per layer (hi, lo).
__global__ void splitT_kernel(const float* __restrict__ src,
                              __nv_bfloat16* __restrict__ dhi,
                              __nv_bfloat16* __restrict__ dlo,
                              int K, int N,
                              size_t srcLayer, size_t dstLayer,
                              int dstRowOff, int dstLd) {
    __shared__ float t[32][33];
    int n0 = blockIdx.x * 32, k0 = blockIdx.y * 32, l = blockIdx.z;
    const float* s = src + (size_t)l * srcLayer;
    int c = threadIdx.x & 31, r8 = threadIdx.x >> 5;
    #pragma unroll
    for (int i = 0; i < 4; i++) {
        int r = r8 + i * 8;
        t[r][c] = s[(size_t)(k0 + r) * N + n0 + c];
    }
    __syncthreads();
    #pragma unroll
    for (int i = 0; i < 4; i++) {
        int rt = r8 + i * 8;                 // n_local
        float x = t[c][rt];                  // (k_local=c, n_local=rt)
        __nv_bfloat16 hi, lo; split_bf16(x, hi, lo);
        size_t o = (size_t)l * dstLayer + (size_t)(dstRowOff + n0 + rt) * dstLd + k0 + c;
        dhi[o] = hi; dlo[o] = lo;
    }
}

// elementwise split (tok_emb: already [V][D] = [n][k])
__global__ void split_kernel(const float* __restrict__ src,
                             __nv_bfloat16* __restrict__ dhi,
                             __nv_bfloat16* __restrict__ dlo, size_t n) {
    for (size_t i = (size_t)blockIdx.x * blockDim.x + threadIdx.x; i < n;
         i += (size_t)gridDim.x * blockDim.x) {
        __nv_bfloat16 hi, lo; split_bf16(src[i], hi, lo);
        dhi[i] = hi; dlo[i] = lo;
    }
}

__global__ void bconcat_kernel(const float* __restrict__ bq,
                               const float* __restrict__ bk,
                               const float* __restrict__ bv,
                               float* __restrict__ o) {
    int l = blockIdx.y;
    int i = blockIdx.x * 256 + threadIdx.x;
    if (i < D_) {
        o[l * QKVN + i]           = bq[l * D_ + i];
        o[l * QKVN + D_ + i]      = bk[l * D_ + i];
        o[l * QKVN + 2 * D_ + i]  = bv[l * D_ + i];
    }
}

// ---------------- embedding ----------------
__global__ void embed_kernel(const int* __restrict__ ids,
                             const float* __restrict__ tok,
                             const float* __restrict__ pos,
                             float* __restrict__ x) {
    int r = blockIdx.x;
    int s = r % S_;
    int id = ids[r];
    const float* t = tok + (size_t)id * D_;
    const float* p = pos + (size_t)s  * D_;
    float* xr = x + (size_t)r * D_;
    for (int d = threadIdx.x; d < D_; d += blockDim.x)
        xr[d] = t[d] + p[d];
}

// ---------------- layernorm -> split bf16 output ----------------
__global__ void ln_kernel(const float* __restrict__ x,
                          const float* __restrict__ g,
                          const float* __restrict__ b,
                          __nv_bfloat16* __restrict__ yhi,
                          __nv_bfloat16* __restrict__ ylo) {
    __shared__ float red[256];
    int r = blockIdx.x;
    int tid = threadIdx.x;
    const float* xr = x + (size_t)r * D_;

    float s = 0.f;
    for (int d = tid; d < D_; d += 256) s += xr[d];
    red[tid] = s; __syncthreads();
    for (int k = 128; k > 0; k >>= 1) {
        if (tid < k) red[tid] += red[tid + k];
        __syncthreads();
    }
    float mean = red[0] * (1.0f / D_);
    __syncthreads();

    float v = 0.f;
    for (int d = tid; d < D_; d += 256) { float t = xr[d] - mean; v += t * t; }
    red[tid] = v; __syncthreads();
    for (int k = 128; k > 0; k >>= 1) {
        if (tid < k) red[tid] += red[tid + k];
        __syncthreads();
    }
    float inv = rsqrtf(red[0] * (1.0f / D_) + EPS_);

    for (int d = tid; d < D_; d += 256) {
        float y = (xr[d] - mean) * inv * g[d] + b[d];
        __nv_bfloat16 hi, lo; split_bf16(y, hi, lo);
        yhi[(size_t)r * D_ + d] = hi;
        ylo[(size_t)r * D_ + d] = lo;
    }
}

// ---------------- bf16x3 tensor-core GEMM ----------------
// C[M,N] = A[M,K] @ B^T[N,K], A/B pre-split bf16 (hi,lo), fp32 accumulate.
// 3 MMAs per fragment: hh + hl + lh.
#define BM 128
#define BK 32

enum { EPI_NONE = 0, EPI_RESID = 1, EPI_GELU_SPLIT = 2 };

template<int BN_>
constexpr int gemm_smem_bytes() { return 32768 + 4 * BN_ * 80; }

template<int EPI, int BN_>
__global__ __launch_bounds__(256, 2)
void bf16x3_gemm(const __nv_bfloat16* __restrict__ Ahi,
                 const __nv_bfloat16* __restrict__ Alo,
                 const __nv_bfloat16* __restrict__ Bhi,
                 const __nv_bfloat16* __restrict__ Blo,
                 const float* __restrict__ bias,
                 const float* __restrict__ resid,
                 float* __restrict__ C,
                 __nv_bfloat16* __restrict__ Chi,
                 __nv_bfloat16* __restrict__ Clo,
                 int M, int N, int K, int ldc) {
    constexpr int NT = (BN_ == 64) ? 4 : 2;
    extern __shared__ __align__(16) char smem_raw[];
    uint32_t sbase = (uint32_t)__cvta_generic_to_shared(smem_raw);

    int tid  = threadIdx.x;
    int lane = tid & 31;
    int warp = tid >> 5;
    int gid  = lane >> 2;
    int tig  = lane & 3;
    int wm   = (warp >> 1) * 32;
    int wn   = (warp & 1) * (BN_ / 2);
    int m0   = blockIdx.y * BM;
    int n0   = blockIdx.x * BN_;

    float acc[2][NT][4];
    #pragma unroll
    for (int i = 0; i < 2; i++)
        #pragma unroll
        for (int j = 0; j < NT; j++)
            #pragma unroll
            for (int e = 0; e < 4; e++) acc[i][j][e] = 0.f;

    auto loadTile = [&](int k0, int bufi) {
        uint32_t sAhi = sbase + bufi * 8192;
        uint32_t sAlo = sbase + 16384 + bufi * 8192;
        uint32_t sBhi = sbase + 32768 + bufi * BN_ * 80;
        uint32_t sBlo = sbase + 32768 + 2 * BN_ * 80 + bufi * BN_ * 80;
        #pragma unroll
        for (int i = 0; i < 2; i++) {
            int cid = tid + i * 256;          // 0..511 over 128 rows x 4 chunks
            int r = cid >> 2, c = cid & 3;
            uint32_t soff = (uint32_t)((r * 4 + (c ^ ((r >> 1) & 3))) * 16);
            size_t go = (size_t)(m0 + r) * K + k0 + c * 8;
            cp16(sAhi + soff, Ahi + go);
            cp16(sAlo + soff, Alo + go);
        }
        for (int cid = tid; cid < BN_ * 4; cid += 256) {
            int r = cid >> 2, c = cid & 3;
            int rr = n0 + r; if (rr > N - 1) rr = N - 1;
            uint32_t soff = (uint32_t)(r * 80 + c * 16);
            size_t go = (size_t)rr * K + k0 + c * 8;
            cp16(sBhi + soff, Bhi + go);
            cp16(sBlo + soff, Blo + go);
        }
    };

    const int nIt = K / BK;
    int buf = 0;
    loadTile(0, 0);
    asm volatile("cp.async.commit_group;\n" ::: "memory");

    for (int it = 0; it < nIt; ++it) {
        asm volatile("cp.async.wait_group 0;\n" ::: "memory");
        __syncthreads();
        if (it + 1 < nIt) {
            loadTile((it + 1) * BK, buf ^ 1);
            asm volatile("cp.async.commit_group;\n" ::: "memory");
        }

        uint32_t sAhiB = sbase + buf * 8192;
        uint32_t sAloB = sbase + 16384 + buf * 8192;
        const char* sBhiB = smem_raw + 32768 + buf * BN_ * 80;
        const char* sBloB = smem_raw + 32768 + 2 * BN_ * 80 + buf * BN_ * 80;

        #pragma unroll
        for (int ks = 0; ks < 2; ks++) {
            uint32_t bh[NT][2], bl[NT][2];
            #pragma unroll
            for (int nt = 0; nt < NT; nt++) {
                int n = wn + nt * 8 + gid;
                const char* ph = sBhiB + n * 80 + ks * 32 + tig * 4;
                const char* pl = sBloB + n * 80 + ks * 32 + tig * 4;
                bh[nt][0] = *(const uint32_t*)ph;
                bh[nt][1] = *(const uint32_t*)(ph + 16);
                bl[nt][0] = *(const uint32_t*)pl;
                bl[nt][1] = *(const uint32_t*)(pl + 16);
            }
            #pragma unroll
            for (int mt = 0; mt < 2; mt++) {
                int r = wm + mt * 16 + (lane & 15);
                int c = ks * 2 + (lane >> 4);
                uint32_t soff = (uint32_t)((r * 4 + (c ^ ((r >> 1) & 3))) * 16);
                uint32_t ah[4], al[4];
                ldm4(ah, sAhiB + soff);
                ldm4(al, sAloB + soff);
                #pragma unroll
                for (int nt = 0; nt < NT; nt++) {
                    mma_bf16(acc[mt][nt], ah, bh[nt]);
                    mma_bf16(acc[mt][nt], ah, bl[nt]);
                    mma_bf16(acc[mt][nt], al, bh[nt]);
                }
            }
        }
        buf ^= 1;
        __syncthreads();
    }

    // ---- epilogue ----
    #pragma unroll
    for (int mt = 0; mt < 2; mt++) {
        #pragma unroll
        for (int nt = 0; nt < NT; nt++) {
            #pragma unroll
            for (int half = 0; half < 2; half++) {
                int gm = m0 + wm + mt * 16 + gid + half * 8;
                int gn0 = n0 + wn + nt * 8 + tig * 2;
                #pragma unroll
                for (int e = 0; e < 2; e++) {
                    int gn = gn0 + e;
                    if (gn >= N) continue;
                    float cv = acc[mt][nt][half * 2 + e];
                    if (bias) cv += bias[gn];
                    size_t o = (size_t)gm * ldc + gn;
                    if (EPI == EPI_RESID) cv += resid[o];
                    if (EPI == EPI_GELU_SPLIT) {
                        cv = 0.5f * cv * (1.0f + erff(cv * 0.70710678118654752f));
                        __nv_bfloat16 hi, lo; split_bf16(cv, hi, lo);
                        Chi[o] = hi; Clo[o] = lo;
                    } else {
                        C[o] = cv;
                    }
                }
            }
        }
    }
}

// ---------------- flash-style causal attention ----------------
// Reads fused qkv [M][2304] fp32; writes split bf16 attention output.
#define ATTN_SMEM_FLOATS 12608

__global__ __launch_bounds__(256)
void attn_flash_kernel(const float* __restrict__ qkv,
                       __nv_bfloat16* __restrict__ ohi,
                       __nv_bfloat16* __restrict__ olo) {
    extern __shared__ float sm[];
    float* sQ  = sm;
    float* sKP = sm + 4160;
    float* sV  = sm + 8320;
    float* salpha = sm + 12480;
    float* slinv  = sm + 12544;

    int qt = blockIdx.x;
    int h  = blockIdx.y;
    int b  = blockIdx.z;
    int tid = threadIdx.x;
    int tx = tid & 15;
    int ty = tid >> 4;
    int q0 = qt * 64;

    #pragma unroll
    for (int i = 0; i < 16; i++) {
        int idx = tid + i * 256;
        int r = idx >> 6, d = idx & 63;
        sQ[d * 65 + r] = qkv[(size_t)(b * S_ + q0 + r) * QKVN + h * DK_ + d] * 0.125f;
    }

    float m_run = -1e30f, l_run = 0.f;
    float Oacc[4][4] = {};
    __syncthreads();

    for (int jt = 0; jt <= qt; jt++) {
        int j0 = jt * 64;
        #pragma unroll
        for (int i = 0; i < 16; i++) {
            int idx = tid + i * 256;
            int r = idx >> 6, d = idx & 63;
            const float* row = qkv + (size_t)(b * S_ + j0 + r) * QKVN + h * DK_ + d;
            sKP[d * 65 + r] = row[D_];        // K
            sV [r * 65 + d] = row[2 * D_];    // V
        }
        __syncthreads();

        float s[4][4] = {};
        #pragma unroll
        for (int kk = 0; kk < 64; kk++) {
            float a[4], bb[4];
            #pragma unroll
            for (int i = 0; i < 4; i++) a[i]  = sQ [kk * 65 + ty * 4 + i];
            #pragma unroll
            for (int j = 0; j < 4; j++) bb[j] = sKP[kk * 65 + tx * 4 + j];
            #pragma unroll
            for (int i = 0; i < 4; i++)
                #pragma unroll
                for (int j = 0; j < 4; j++)
                    s[i][j] += a[i] * bb[j];
        }
        __syncthreads();

        bool diag = (jt == qt);
        #pragma unroll
        for (int i = 0; i < 4; i++)
            #pragma unroll
            for (int j = 0; j < 4; j++) {
                float val = s[i][j];
                if (diag && (tx * 4 + j) > (ty * 4 + i)) val = -1e30f;
                sKP[(tx * 4 + j) * 65 + (ty * 4 + i)] = val;
            }
        __syncthreads();

        if (tid < 64) {
            int qr = tid;
            float mt = -1e30f;
            #pragma unroll 4
            for (int j = 0; j < 64; j++) mt = fmaxf(mt, sKP[j * 65 + qr]);
            float m_new = fmaxf(m_run, mt);
            float alpha = __expf(m_run - m_new);
            float lsum = 0.f;
            #pragma unroll 4
            for (int j = 0; j < 64; j++) {
                float e = __expf(sKP[j * 65 + qr] - m_new);
                sKP[j * 65 + qr] = e;
                lsum += e;
            }
            l_run = l_run * alpha + lsum;
            m_run = m_new;
            salpha[qr] = alpha;
        }
        __syncthreads();

        #pragma unroll
        for (int i = 0; i < 4; i++) {
            float al = salpha[ty * 4 + i];
            #pragma unroll
            for (int j = 0; j < 4; j++) Oacc[i][j] *= al;
        }
        #pragma unroll
        for (int kk = 0; kk < 64; kk++) {
            float a[4], bb[4];
            #pragma unroll
            for (int i = 0; i < 4; i++) a[i]  = sKP[kk * 65 + ty * 4 + i];
            #pragma unroll
            for (int j = 0; j < 4; j++) bb[j] = sV [kk * 65 + tx * 4 + j];
            #pragma unroll
            for (int i = 0; i < 4; i++)
                #pragma unroll
                for (int j = 0; j < 4; j++)
                    Oacc[i][j] += a[i] * bb[j];
        }
        __syncthreads();
    }

    if (tid < 64) slinv[tid] = 1.0f / l_run;
    __syncthreads();

    #pragma unroll
    for (int i = 0; i < 4; i++) {
        int qr = ty * 4 + i;
        float inv = slinv[qr];
        size_t o = (size_t)(b * S_ + q0 + qr) * D_ + h * DK_ + tx * 4;
        #pragma unroll
        for (int j = 0; j < 4; j++) {
            __nv_bfloat16 hi, lo; split_bf16(Oacc[i][j] * inv, hi, lo);
            ohi[o + j] = hi; olo[o + j] = lo;
        }
    }
}

// ---------------- host orchestration ----------------
extern "C" void kernel_launch(void* const* d_in, const int* in_sizes, int n_in,
                              void* d_out, int out_size) {
    const int*   ids   = (const int*)  d_in[0];
    const float* tok   = (const float*)d_in[1];
    const float* pos   = (const float*)d_in[2];
    const float* wq    = (const float*)d_in[3];
    const float* bq    = (const float*)d_in[4];
    const float* wk    = (const float*)d_in[5];
    const float* bk    = (const float*)d_in[6];
    const float* wv    = (const float*)d_in[7];
    const float* bv    = (const float*)d_in[8];
    const float* wo    = (const float*)d_in[9];
    const float* bo    = (const float*)d_in[10];
    const float* w1    = (const float*)d_in[11];
    const float* b1    = (const float*)d_in[12];
    const float* w2    = (const float*)d_in[13];
    const float* b2    = (const float*)d_in[14];
    const float* ln1g  = (const float*)d_in[15];
    const float* ln1b  = (const float*)d_in[16];
    const float* ln2g  = (const float*)d_in[17];
    const float* ln2b  = (const float*)d_in[18];
    const float* lnfg  = (const float*)d_in[19];
    const float* lnfb  = (const float*)d_in[20];
    float* out = (float*)d_out;

    float *x, *qkv, *bqkv;
    __nv_bfloat16 *hhi, *hlo, *atthi, *attlo, *ffhi, *fflo;
    __nv_bfloat16 *wqkvhi, *wqkvlo, *wohi, *wolo, *w1hi, *w1lo, *w2hi, *w2lo, *tokhi, *toklo;
    cudaGetSymbolAddress((void**)&x,      g_x);
    cudaGetSymbolAddress((void**)&qkv,    g_qkv);
    cudaGetSymbolAddress((void**)&bqkv,   g_bqkv);
    cudaGetSymbolAddress((void**)&hhi,    g_h_hi);
    cudaGetSymbolAddress((void**)&hlo,    g_h_lo);
    cudaGetSymbolAddress((void**)&atthi,  g_att_hi);
    cudaGetSymbolAddress((void**)&attlo,  g_att_lo);
    cudaGetSymbolAddress((void**)&ffhi,   g_ff_hi);
    cudaGetSymbolAddress((void**)&fflo,   g_ff_lo);
    cudaGetSymbolAddress((void**)&wqkvhi, g_wqkv_hi);
    cudaGetSymbolAddress((void**)&wqkvlo, g_wqkv_lo);
    cudaGetSymbolAddress((void**)&wohi,   g_wo_hi);
    cudaGetSymbolAddress((void**)&wolo,   g_wo_lo);
    cudaGetSymbolAddress((void**)&w1hi,   g_w1_hi);
    cudaGetSymbolAddress((void**)&w1lo,   g_w1_lo);
    cudaGetSymbolAddress((void**)&w2hi,   g_w2_hi);
    cudaGetSymbolAddress((void**)&w2lo,   g_w2_lo);
    cudaGetSymbolAddress((void**)&tokhi,  g_tok_hi);
    cudaGetSymbolAddress((void**)&toklo,  g_tok_lo);

    // smem attributes
    const int gemmSmem64 = gemm_smem_bytes<64>();
    const int gemmSmem32 = gemm_smem_bytes<32>();
    cudaFuncSetAttribute(bf16x3_gemm<EPI_NONE, 64>,
                         cudaFuncAttributeMaxDynamicSharedMemorySize, gemmSmem64);
    cudaFuncSetAttribute(bf16x3_gemm<EPI_GELU_SPLIT, 64>,
                         cudaFuncAttributeMaxDynamicSharedMemorySize, gemmSmem64);
    cudaFuncSetAttribute(bf16x3_gemm<EPI_RESID, 32>,
                         cudaFuncAttributeMaxDynamicSharedMemorySize, gemmSmem32);
    const int attnSmem = ATTN_SMEM_FLOATS * sizeof(float);
    cudaFuncSetAttribute(attn_flash_kernel,
                         cudaFuncAttributeMaxDynamicSharedMemorySize, attnSmem);

    // ---- prepass: weight splitting / transposition ----
    splitT_kernel<<<dim3(D_/32, D_/32, L_), 256>>>(
        wq, wqkvhi, wqkvlo, D_, D_, (size_t)D_*D_, (size_t)QKVN*D_, 0,     D_);
    splitT_kernel<<<dim3(D_/32, D_/32, L_), 256>>>(
        wk, wqkvhi, wqkvlo, D_, D_, (size_t)D_*D_, (size_t)QKVN*D_, D_,    D_);
    splitT_kernel<<<dim3(D_/32, D_/32, L_), 256>>>(
        wv, wqkvhi, wqkvlo, D_, D_, (size_t)D_*D_, (size_t)QKVN*D_, 2*D_,  D_);
    splitT_kernel<<<dim3(D_/32, D_/32, L_), 256>>>(
        wo, wohi, wolo, D_, D_, (size_t)D_*D_, (size_t)D_*D_, 0, D_);
    splitT_kernel<<<dim3(DF_/32, D_/32, L_), 256>>>(
        w1, w1hi, w1lo, D_, DF_, (size_t)D_*DF_, (size_t)DF_*D_, 0, D_);
    splitT_kernel<<<dim3(D_/32, DF_/32, L_), 256>>>(
        w2, w2hi, w2lo, DF_, D_, (size_t)DF_*D_, (size_t)D_*DF_, 0, DF_);
    split_kernel<<<2048, 256>>>(tok, tokhi, toklo, (size_t)V_ * D_);
    bconcat_kernel<<<dim3(3, L_), 256>>>(bq, bk, bv, bqkv);

    embed_kernel<<<M_, 256>>>(ids, tok, pos, x);

    for (int l = 0; l < L_; l++) {
        ln_kernel<<<M_, 256>>>(x, ln1g + l * D_, ln1b + l * D_, hhi, hlo);

        // fused QKV GEMM: [1024,2304] = h @ Wqkv^T
        bf16x3_gemm<EPI_NONE, 64><<<dim3(QKVN/64, M_/BM), 256, gemmSmem64>>>(
            hhi, hlo,
            wqkvhi + (size_t)l * QKVN * D_, wqkvlo + (size_t)l * QKVN * D_,
            bqkv + l * QKVN, nullptr, qkv, nullptr, nullptr,
            M_, QKVN, D_, QKVN);

        attn_flash_kernel<<<dim3(8, H_, B_), 256, attnSmem>>>(qkv, atthi, attlo);

        // output projection + residual
        bf16x3_gemm<EPI_RESID, 32><<<dim3(D_/32, M_/BM), 256, gemmSmem32>>>(
            atthi, attlo,
            wohi + (size_t)l * D_ * D_, wolo + (size_t)l * D_ * D_,
            bo + l * D_, x, x, nullptr, nullptr,
            M_, D_, D_, D_);

        ln_kernel<<<M_, 256>>>(x, ln2g + l * D_, ln2b + l * D_, hhi, hlo);

        // MLP up + GELU (split output)
        bf16x3_gemm<EPI_GELU_SPLIT, 64><<<dim3(DF_/64, M_/BM), 256, gemmSmem64>>>(
            hhi, hlo,
            w1hi + (size_t)l * DF_ * D_, w1lo + (size_t)l * DF_ * D_,
            b1 + l * DF_, nullptr, nullptr, ffhi, fflo,
            M_, DF_, D_, DF_);

        // MLP down + residual
        bf16x3_gemm<EPI_RESID, 32><<<dim3(D_/32, M_/BM), 256, gemmSmem32>>>(
            ffhi, fflo,
            w2hi + (size_t)l * D_ * DF_, w2lo + (size_t)l * D_ * DF_,
            b2 + l * D_, x, x, nullptr, nullptr,
            M_, D_, DF_, D_);
    }

    ln_kernel<<<M_, 256>>>(x, lnfg, lnfb, hhi, hlo);

    // tied lm_head: logits = h @ tok^T
    bf16x3_gemm<EPI_NONE, 64><<<dim3((V_ + 63) / 64, M_/BM), 256, gemmSmem64>>>(
        hhi, hlo, tokhi, toklo,
        nullptr, nullptr, out, nullptr, nullptr,
        M_, V_, D_, V_);
}

// round 6
// speedup vs baseline: 5.3875x; 1.1005x over previous
#include <cuda_runtime.h>
#include <cuda_bf16.h>
#include <stdint.h>
#include <math.h>

// ---------------- problem constants ----------------
#define B_    2
#define S_    512
#define M_    1024
#define D_    768
#define H_    12
#define DK_   64
#define DF_   3072
#define L_    12
#define V_    50257
#define QKVN  (3 * D_)     // 2304
#define EPS_  1e-5f

// ---------------- scratch (device globals) ----------------
__device__ float          g_x[M_ * D_];
__device__ __nv_bfloat16  g_h_hi[M_ * D_],  g_h_lo[M_ * D_];
__device__ float          g_qkv[M_ * QKVN];
__device__ __nv_bfloat16  g_att_hi[M_ * D_], g_att_lo[M_ * D_];
__device__ __nv_bfloat16  g_ff_hi[M_ * DF_], g_ff_lo[M_ * DF_];
__device__ __nv_bfloat16  g_wqkv_hi[L_ * QKVN * D_], g_wqkv_lo[L_ * QKVN * D_];
__device__ __nv_bfloat16  g_wo_hi[L_ * D_ * D_],     g_wo_lo[L_ * D_ * D_];
__device__ __nv_bfloat16  g_w1_hi[L_ * DF_ * D_],    g_w1_lo[L_ * DF_ * D_];
__device__ __nv_bfloat16  g_w2_hi[L_ * D_ * DF_],    g_w2_lo[L_ * D_ * DF_];
__device__ __nv_bfloat16  g_tok_hi[(size_t)V_ * D_], g_tok_lo[(size_t)V_ * D_];
__device__ float          g_bqkv[L_ * QKVN];

// ---------------- small helpers ----------------
__device__ __forceinline__ void split_bf16(float x, __nv_bfloat16& hi, __nv_bfloat16& lo) {
    hi = __float2bfloat16(x);
    lo = __float2bfloat16(x - __bfloat162float(hi));
}

__device__ __forceinline__ uint32_t pack2(float lo, float hi) {
    __nv_bfloat162 t = __floats2bfloat162_rn(lo, hi);   // x = lo (low half), y = hi
    return *(uint32_t*)&t;
}

__device__ __forceinline__ void cp16(uint32_t saddr, const void* g) {
    asm volatile("cp.async.cg.shared.global [%0], [%1], 16;\n" :: "r"(saddr), "l"(g));
}

__device__ __forceinline__ void ldm4(uint32_t a[4], uint32_t saddr) {
    asm volatile("ldmatrix.sync.aligned.m8n8.x4.shared.b16 {%0,%1,%2,%3}, [%4];"
                 : "=r"(a[0]), "=r"(a[1]), "=r"(a[2]), "=r"(a[3]) : "r"(saddr));
}

__device__ __forceinline__ void mma_bf16(float c[4], const uint32_t a[4], const uint32_t b[2]) {
    asm volatile("mma.sync.aligned.m16n8k16.row.col.f32.bf16.bf16.f32 "
                 "{%0,%1,%2,%3}, {%4,%5,%6,%7}, {%8,%9}, {%0,%1,%2,%3};"
                 : "+f"(c[0]), "+f"(c[1]), "+f"(c[2]), "+f"(c[3])
                 : "r"(a[0]), "r"(a[1]), "r"(a[2]), "r"(a[3]),
                   "r"(b[0]), "r"(b[1]));
}

// ---------------- prepass: split+transpose weights ----------------
__global__ void splitT_kernel(const float* __restrict__ src,
                              __nv_bfloat16* __restrict__ dhi,
                              __nv_bfloat16* __restrict__ dlo,
                              int K, int N,
                              size_t srcLayer, size_t dstLayer,
                              int dstRowOff, int dstLd) {
    __shared__ float t[32][33];
    int n0 = blockIdx.x * 32, k0 = blockIdx.y * 32, l = blockIdx.z;
    const float* s = src + (size_t)l * srcLayer;
    int c = threadIdx.x & 31, r8 = threadIdx.x >> 5;
    #pragma unroll
    for (int i = 0; i < 4; i++) {
        int r = r8 + i * 8;
        t[r][c] = s[(size_t)(k0 + r) * N + n0 + c];
    }
    __syncthreads();
    #pragma unroll
    for (int i = 0; i < 4; i++) {
        int rt = r8 + i * 8;
        float x = t[c][rt];
        __nv_bfloat16 hi, lo; split_bf16(x, hi, lo);
        size_t o = (size_t)l * dstLayer + (size_t)(dstRowOff + n0 + rt) * dstLd + k0 + c;
        dhi[o] = hi; dlo[o] = lo;
    }
}

__global__ void split_kernel(const float* __restrict__ src,
                             __nv_bfloat16* __restrict__ dhi,
                             __nv_bfloat16* __restrict__ dlo, size_t n) {
    for (size_t i = (size_t)blockIdx.x * blockDim.x + threadIdx.x; i < n;
         i += (size_t)gridDim.x * blockDim.x) {
        __nv_bfloat16 hi, lo; split_bf16(src[i], hi, lo);
        dhi[i] = hi; dlo[i] = lo;
    }
}

__global__ void bconcat_kernel(const float* __restrict__ bq,
                               const float* __restrict__ bk,
                               const float* __restrict__ bv,
                               float* __restrict__ o) {
    int l = blockIdx.y;
    int i = blockIdx.x * 256 + threadIdx.x;
    if (i < D_) {
        o[l * QKVN + i]           = bq[l * D_ + i];
        o[l * QKVN + D_ + i]      = bk[l * D_ + i];
        o[l * QKVN + 2 * D_ + i]  = bv[l * D_ + i];
    }
}

// ---------------- embedding ----------------
__global__ void embed_kernel(const int* __restrict__ ids,
                             const float* __restrict__ tok,
                             const float* __restrict__ pos,
                             float* __restrict__ x) {
    int r = blockIdx.x;
    int s = r % S_;
    int id = ids[r];
    const float* t = tok + (size_t)id * D_;
    const float* p = pos + (size_t)s  * D_;
    float* xr = x + (size_t)r * D_;
    for (int d = threadIdx.x; d < D_; d += blockDim.x)
        xr[d] = t[d] + p[d];
}

// ---------------- layernorm -> split bf16 output ----------------
__global__ void ln_kernel(const float* __restrict__ x,
                          const float* __restrict__ g,
                          const float* __restrict__ b,
                          __nv_bfloat16* __restrict__ yhi,
                          __nv_bfloat16* __restrict__ ylo) {
    __shared__ float red[256];
    int r = blockIdx.x;
    int tid = threadIdx.x;
    const float* xr = x + (size_t)r * D_;

    float s = 0.f;
    for (int d = tid; d < D_; d += 256) s += xr[d];
    red[tid] = s; __syncthreads();
    for (int k = 128; k > 0; k >>= 1) {
        if (tid < k) red[tid] += red[tid + k];
        __syncthreads();
    }
    float mean = red[0] * (1.0f / D_);
    __syncthreads();

    float v = 0.f;
    for (int d = tid; d < D_; d += 256) { float t = xr[d] - mean; v += t * t; }
    red[tid] = v; __syncthreads();
    for (int k = 128; k > 0; k >>= 1) {
        if (tid < k) red[tid] += red[tid + k];
        __syncthreads();
    }
    float inv = rsqrtf(red[0] * (1.0f / D_) + EPS_);

    for (int d = tid; d < D_; d += 256) {
        float y = (xr[d] - mean) * inv * g[d] + b[d];
        __nv_bfloat16 hi, lo; split_bf16(y, hi, lo);
        yhi[(size_t)r * D_ + d] = hi;
        ylo[(size_t)r * D_ + d] = lo;
    }
}

// ---------------- bf16x3 tensor-core GEMM ----------------
#define BM 128
#define BK 32

enum { EPI_NONE = 0, EPI_RESID = 1, EPI_GELU_SPLIT = 2 };

template<int BN_>
constexpr int gemm_smem_bytes() { return 32768 + 4 * BN_ * 80; }

template<int EPI, int BN_>
__global__ __launch_bounds__(256, 2)
void bf16x3_gemm(const __nv_bfloat16* __restrict__ Ahi,
                 const __nv_bfloat16* __restrict__ Alo,
                 const __nv_bfloat16* __restrict__ Bhi,
                 const __nv_bfloat16* __restrict__ Blo,
                 const float* __restrict__ bias,
                 const float* __restrict__ resid,
                 float* __restrict__ C,
                 __nv_bfloat16* __restrict__ Chi,
                 __nv_bfloat16* __restrict__ Clo,
                 int M, int N, int K, int ldc) {
    constexpr int NT = (BN_ == 64) ? 4 : 2;
    extern __shared__ __align__(16) char smem_raw[];
    uint32_t sbase = (uint32_t)__cvta_generic_to_shared(smem_raw);

    int tid  = threadIdx.x;
    int lane = tid & 31;
    int warp = tid >> 5;
    int gid  = lane >> 2;
    int tig  = lane & 3;
    int wm   = (warp >> 1) * 32;
    int wn   = (warp & 1) * (BN_ / 2);
    int m0   = blockIdx.y * BM;
    int n0   = blockIdx.x * BN_;

    float acc[2][NT][4];
    #pragma unroll
    for (int i = 0; i < 2; i++)
        #pragma unroll
        for (int j = 0; j < NT; j++)
            #pragma unroll
            for (int e = 0; e < 4; e++) acc[i][j][e] = 0.f;

    auto loadTile = [&](int k0, int bufi) {
        uint32_t sAhi = sbase + bufi * 8192;
        uint32_t sAlo = sbase + 16384 + bufi * 8192;
        uint32_t sBhi = sbase + 32768 + bufi * BN_ * 80;
        uint32_t sBlo = sbase + 32768 + 2 * BN_ * 80 + bufi * BN_ * 80;
        #pragma unroll
        for (int i = 0; i < 2; i++) {
            int cid = tid + i * 256;
            int r = cid >> 2, c = cid & 3;
            uint32_t soff = (uint32_t)((r * 4 + (c ^ ((r >> 1) & 3))) * 16);
            size_t go = (size_t)(m0 + r) * K + k0 + c * 8;
            cp16(sAhi + soff, Ahi + go);
            cp16(sAlo + soff, Alo + go);
        }
        for (int cid = tid; cid < BN_ * 4; cid += 256) {
            int r = cid >> 2, c = cid & 3;
            int rr = n0 + r; if (rr > N - 1) rr = N - 1;
            uint32_t soff = (uint32_t)(r * 80 + c * 16);
            size_t go = (size_t)rr * K + k0 + c * 8;
            cp16(sBhi + soff, Bhi + go);
            cp16(sBlo + soff, Blo + go);
        }
    };

    const int nIt = K / BK;
    int buf = 0;
    loadTile(0, 0);
    asm volatile("cp.async.commit_group;\n" ::: "memory");

    for (int it = 0; it < nIt; ++it) {
        asm volatile("cp.async.wait_group 0;\n" ::: "memory");
        __syncthreads();
        if (it + 1 < nIt) {
            loadTile((it + 1) * BK, buf ^ 1);
            asm volatile("cp.async.commit_group;\n" ::: "memory");
        }

        uint32_t sAhiB = sbase + buf * 8192;
        uint32_t sAloB = sbase + 16384 + buf * 8192;
        const char* sBhiB = smem_raw + 32768 + buf * BN_ * 80;
        const char* sBloB = smem_raw + 32768 + 2 * BN_ * 80 + buf * BN_ * 80;

        #pragma unroll
        for (int ks = 0; ks < 2; ks++) {
            uint32_t bh[NT][2], bl[NT][2];
            #pragma unroll
            for (int nt = 0; nt < NT; nt++) {
                int n = wn + nt * 8 + gid;
                const char* ph = sBhiB + n * 80 + ks * 32 + tig * 4;
                const char* pl = sBloB + n * 80 + ks * 32 + tig * 4;
                bh[nt][0] = *(const uint32_t*)ph;
                bh[nt][1] = *(const uint32_t*)(ph + 16);
                bl[nt][0] = *(const uint32_t*)pl;
                bl[nt][1] = *(const uint32_t*)(pl + 16);
            }
            #pragma unroll
            for (int mt = 0; mt < 2; mt++) {
                int r = wm + mt * 16 + (lane & 15);
                int c = ks * 2 + (lane >> 4);
                uint32_t soff = (uint32_t)((r * 4 + (c ^ ((r >> 1) & 3))) * 16);
                uint32_t ah[4], al[4];
                ldm4(ah, sAhiB + soff);
                ldm4(al, sAloB + soff);
                #pragma unroll
                for (int nt = 0; nt < NT; nt++) {
                    mma_bf16(acc[mt][nt], ah, bh[nt]);
                    mma_bf16(acc[mt][nt], ah, bl[nt]);
                    mma_bf16(acc[mt][nt], al, bh[nt]);
                }
            }
        }
        buf ^= 1;
        __syncthreads();
    }

    #pragma unroll
    for (int mt = 0; mt < 2; mt++) {
        #pragma unroll
        for (int nt = 0; nt < NT; nt++) {
            #pragma unroll
            for (int half = 0; half < 2; half++) {
                int gm = m0 + wm + mt * 16 + gid + half * 8;
                int gn0 = n0 + wn + nt * 8 + tig * 2;
                #pragma unroll
                for (int e = 0; e < 2; e++) {
                    int gn = gn0 + e;
                    if (gn >= N) continue;
                    float cv = acc[mt][nt][half * 2 + e];
                    if (bias) cv += bias[gn];
                    size_t o = (size_t)gm * ldc + gn;
                    if (EPI == EPI_RESID) cv += resid[o];
                    if (EPI == EPI_GELU_SPLIT) {
                        cv = 0.5f * cv * (1.0f + erff(cv * 0.70710678118654752f));
                        __nv_bfloat16 hi, lo; split_bf16(cv, hi, lo);
                        Chi[o] = hi; Clo[o] = lo;
                    } else {
                        C[o] = cv;
                    }
                }
            }
        }
    }
}

// ---------------- tensor-core flash attention ----------------
// One block per (b, h, 64-q tile); 4 warps, 16 q-rows each.
// bf16x3 (hi/lo split) for both Q@K^T and P@V; fp32 softmax in registers.
// SMEM (bf16, pitch 66): Qhi Qlo Khi Klo VThi VTlo -> 6 * 64*66 * 2B = 50688 B
#define APITCH 66
#define ATTN_SMEM_BYTES (6 * 64 * APITCH * 2)

__global__ __launch_bounds__(128)
void attn_mma_kernel(const float* __restrict__ qkv,
                     __nv_bfloat16* __restrict__ ohi,
                     __nv_bfloat16* __restrict__ olo) {
    extern __shared__ __nv_bfloat16 sb[];
    __nv_bfloat16* sQh = sb;
    __nv_bfloat16* sQl = sb + 1 * 64 * APITCH;
    __nv_bfloat16* sKh = sb + 2 * 64 * APITCH;
    __nv_bfloat16* sKl = sb + 3 * 64 * APITCH;
    __nv_bfloat16* sVh = sb + 4 * 64 * APITCH;   // transposed: [d][j]
    __nv_bfloat16* sVl = sb + 5 * 64 * APITCH;

    int qt = 7 - blockIdx.x;        // heavy tiles first
    int h  = blockIdx.y;
    int b  = blockIdx.z;
    int tid  = threadIdx.x;
    int lane = tid & 31;
    int warp = tid >> 5;
    int gid  = lane >> 2;
    int tig  = lane & 3;
    int q0 = qt * 64;
    int rowbase = warp * 16;        // warp's first q-row within tile

    // load + split Q (pre-scaled)
    #pragma unroll
    for (int i = 0; i < 32; i++) {
        int idx = tid + i * 128;
        int r = idx >> 6, d = idx & 63;
        float qv = qkv[(size_t)(b * S_ + q0 + r) * QKVN + h * DK_ + d] * 0.125f;
        __nv_bfloat16 hi, lo; split_bf16(qv, hi, lo);
        sQh[r * APITCH + d] = hi;
        sQl[r * APITCH + d] = lo;
    }
    __syncthreads();

    float m0r = -1e30f, m1r = -1e30f;
    float l0r = 0.f,    l1r = 0.f;
    float oacc[8][4];
    #pragma unroll
    for (int i = 0; i < 8; i++)
        #pragma unroll
        for (int e = 0; e < 4; e++) oacc[i][e] = 0.f;

    for (int jt = 0; jt <= qt; jt++) {
        // load + split K ([j][d]) and V (transposed [d][j])
        #pragma unroll
        for (int i = 0; i < 32; i++) {
            int idx = tid + i * 128;
            int r = idx >> 6, d = idx & 63;
            const float* base = qkv + (size_t)(b * S_ + jt * 64 + r) * QKVN + h * DK_ + d;
            float kv = base[D_];
            float vv = base[2 * D_];
            __nv_bfloat16 hi, lo;
            split_bf16(kv, hi, lo);
            sKh[r * APITCH + d] = hi;
            sKl[r * APITCH + d] = lo;
            split_bf16(vv, hi, lo);
            sVh[d * APITCH + r] = hi;
            sVl[d * APITCH + r] = lo;
        }
        __syncthreads();

        // ---- scores: S[16 x 64] per warp ----
        float sc[8][4];
        #pragma unroll
        for (int i = 0; i < 8; i++)
            #pragma unroll
            for (int e = 0; e < 4; e++) sc[i][e] = 0.f;

        #pragma unroll
        for (int ks = 0; ks < 4; ks++) {
            int r0 = rowbase + gid, r1 = rowbase + gid + 8;
            int kc = ks * 16 + 2 * tig;
            uint32_t ah[4], al[4];
            ah[0] = *(uint32_t*)&sQh[r0 * APITCH + kc];
            ah[1] = *(uint32_t*)&sQh[r1 * APITCH + kc];
            ah[2] = *(uint32_t*)&sQh[r0 * APITCH + kc + 8];
            ah[3] = *(uint32_t*)&sQh[r1 * APITCH + kc + 8];
            al[0] = *(uint32_t*)&sQl[r0 * APITCH + kc];
            al[1] = *(uint32_t*)&sQl[r1 * APITCH + kc];
            al[2] = *(uint32_t*)&sQl[r0 * APITCH + kc + 8];
            al[3] = *(uint32_t*)&sQl[r1 * APITCH + kc + 8];
            #pragma unroll
            for (int nf = 0; nf < 8; nf++) {
                int n = nf * 8 + gid;
                uint32_t bh[2], bl[2];
                bh[0] = *(uint32_t*)&sKh[n * APITCH + kc];
                bh[1] = *(uint32_t*)&sKh[n * APITCH + kc + 8];
                bl[0] = *(uint32_t*)&sKl[n * APITCH + kc];
                bl[1] = *(uint32_t*)&sKl[n * APITCH + kc + 8];
                mma_bf16(sc[nf], ah, bh);
                mma_bf16(sc[nf], ah, bl);
                mma_bf16(sc[nf], al, bh);
            }
        }

        // ---- causal mask on diagonal tile ----
        if (jt == qt) {
            int ql0 = rowbase + gid, ql1 = ql0 + 8;
            #pragma unroll
            for (int nf = 0; nf < 8; nf++) {
                int j0 = nf * 8 + 2 * tig;
                if (j0     > ql0) sc[nf][0] = -1e30f;
                if (j0 + 1 > ql0) sc[nf][1] = -1e30f;
                if (j0     > ql1) sc[nf][2] = -1e30f;
                if (j0 + 1 > ql1) sc[nf][3] = -1e30f;
            }
        }

        // ---- online softmax (rows gid and gid+8) ----
        float mx0 = -1e30f, mx1 = -1e30f;
        #pragma unroll
        for (int nf = 0; nf < 8; nf++) {
            mx0 = fmaxf(mx0, fmaxf(sc[nf][0], sc[nf][1]));
            mx1 = fmaxf(mx1, fmaxf(sc[nf][2], sc[nf][3]));
        }
        mx0 = fmaxf(mx0, __shfl_xor_sync(0xffffffff, mx0, 1));
        mx0 = fmaxf(mx0, __shfl_xor_sync(0xffffffff, mx0, 2));
        mx1 = fmaxf(mx1, __shfl_xor_sync(0xffffffff, mx1, 1));
        mx1 = fmaxf(mx1, __shfl_xor_sync(0xffffffff, mx1, 2));

        float mn0 = fmaxf(m0r, mx0), mn1 = fmaxf(m1r, mx1);
        float al0 = __expf(m0r - mn0), al1 = __expf(m1r - mn1);
        m0r = mn0; m1r = mn1;

        float sum0 = 0.f, sum1 = 0.f;
        #pragma unroll
        for (int nf = 0; nf < 8; nf++) {
            sc[nf][0] = __expf(sc[nf][0] - mn0);
            sc[nf][1] = __expf(sc[nf][1] - mn0);
            sc[nf][2] = __expf(sc[nf][2] - mn1);
            sc[nf][3] = __expf(sc[nf][3] - mn1);
            sum0 += sc[nf][0] + sc[nf][1];
            sum1 += sc[nf][2] + sc[nf][3];
        }
        sum0 += __shfl_xor_sync(0xffffffff, sum0, 1);
        sum0 += __shfl_xor_sync(0xffffffff, sum0, 2);
        sum1 += __shfl_xor_sync(0xffffffff, sum1, 1);
        sum1 += __shfl_xor_sync(0xffffffff, sum1, 2);
        l0r = l0r * al0 + sum0;
        l1r = l1r * al1 + sum1;

        // rescale O
        #pragma unroll
        for (int df = 0; df < 8; df++) {
            oacc[df][0] *= al0; oacc[df][1] *= al0;
            oacc[df][2] *= al1; oacc[df][3] *= al1;
        }

        // ---- P @ V : P c-frags -> a-frags (hi/lo), V from transposed smem ----
        #pragma unroll
        for (int ks = 0; ks < 4; ks++) {
            int f0 = 2 * ks, f1 = 2 * ks + 1;
            // split P into bf16 hi / lo
            float h00 = __bfloat162float(__float2bfloat16(sc[f0][0]));
            float h01 = __bfloat162float(__float2bfloat16(sc[f0][1]));
            float h02 = __bfloat162float(__float2bfloat16(sc[f0][2]));
            float h03 = __bfloat162float(__float2bfloat16(sc[f0][3]));
            float h10 = __bfloat162float(__float2bfloat16(sc[f1][0]));
            float h11 = __bfloat162float(__float2bfloat16(sc[f1][1]));
            float h12 = __bfloat162float(__float2bfloat16(sc[f1][2]));
            float h13 = __bfloat162float(__float2bfloat16(sc[f1][3]));
            uint32_t ph[4], pl[4];
            ph[0] = pack2(h00, h01);
            ph[1] = pack2(h02, h03);
            ph[2] = pack2(h10, h11);
            ph[3] = pack2(h12, h13);
            pl[0] = pack2(sc[f0][0] - h00, sc[f0][1] - h01);
            pl[1] = pack2(sc[f0][2] - h02, sc[f0][3] - h03);
            pl[2] = pack2(sc[f1][0] - h10, sc[f1][1] - h11);
            pl[3] = pack2(sc[f1][2] - h12, sc[f1][3] - h13);

            int kc = ks * 16 + 2 * tig;
            #pragma unroll
            for (int df = 0; df < 8; df++) {
                int d = df * 8 + gid;
                uint32_t bh[2], bl[2];
                bh[0] = *(uint32_t*)&sVh[d * APITCH + kc];
                bh[1] = *(uint32_t*)&sVh[d * APITCH + kc + 8];
                bl[0] = *(uint32_t*)&sVl[d * APITCH + kc];
                bl[1] = *(uint32_t*)&sVl[d * APITCH + kc + 8];
                mma_bf16(oacc[df], ph, bh);
                mma_bf16(oacc[df], ph, bl);
                mma_bf16(oacc[df], pl, bh);
            }
        }
        __syncthreads();   // before next tile overwrites K/V smem
    }

    // ---- epilogue: normalize, split, store ----
    float inv0 = 1.0f / l0r, inv1 = 1.0f / l1r;
    int r0 = b * S_ + q0 + rowbase + gid;
    int r1 = r0 + 8;
    #pragma unroll
    for (int df = 0; df < 8; df++) {
        int d = h * DK_ + df * 8 + 2 * tig;
        float o0 = oacc[df][0] * inv0, o1 = oacc[df][1] * inv0;
        float o2 = oacc[df][2] * inv1, o3 = oacc[df][3] * inv1;
        __nv_bfloat16 hi0, lo0, hi1, lo1;
        split_bf16(o0, hi0, lo0); split_bf16(o1, hi1, lo1);
        *(uint32_t*)&ohi[(size_t)r0 * D_ + d] = pack2(__bfloat162float(hi0), __bfloat162float(hi1));
        *(uint32_t*)&olo[(size_t)r0 * D_ + d] = pack2(__bfloat162float(lo0), __bfloat162float(lo1));
        split_bf16(o2, hi0, lo0); split_bf16(o3, hi1, lo1);
        *(uint32_t*)&ohi[(size_t)r1 * D_ + d] = pack2(__bfloat162float(hi0), __bfloat162float(hi1));
        *(uint32_t*)&olo[(size_t)r1 * D_ + d] = pack2(__bfloat162float(lo0), __bfloat162float(lo1));
    }
}

// ---------------- host orchestration ----------------
extern "C" void kernel_launch(void* const* d_in, const int* in_sizes, int n_in,
                              void* d_out, int out_size) {
    const int*   ids   = (const int*)  d_in[0];
    const float* tok   = (const float*)d_in[1];
    const float* pos   = (const float*)d_in[2];
    const float* wq    = (const float*)d_in[3];
    const float* bq    = (const float*)d_in[4];
    const float* wk    = (const float*)d_in[5];
    const float* bk    = (const float*)d_in[6];
    const float* wv    = (const float*)d_in[7];
    const float* bv    = (const float*)d_in[8];
    const float* wo    = (const float*)d_in[9];
    const float* bo    = (const float*)d_in[10];
    const float* w1    = (const float*)d_in[11];
    const float* b1    = (const float*)d_in[12];
    const float* w2    = (const float*)d_in[13];
    const float* b2    = (const float*)d_in[14];
    const float* ln1g  = (const float*)d_in[15];
    const float* ln1b  = (const float*)d_in[16];
    const float* ln2g  = (const float*)d_in[17];
    const float* ln2b  = (const float*)d_in[18];
    const float* lnfg  = (const float*)d_in[19];
    const float* lnfb  = (const float*)d_in[20];
    float* out = (float*)d_out;

    float *x, *qkv, *bqkv;
    __nv_bfloat16 *hhi, *hlo, *atthi, *attlo, *ffhi, *fflo;
    __nv_bfloat16 *wqkvhi, *wqkvlo, *wohi, *wolo, *w1hi, *w1lo, *w2hi, *w2lo, *tokhi, *toklo;
    cudaGetSymbolAddress((void**)&x,      g_x);
    cudaGetSymbolAddress((void**)&qkv,    g_qkv);
    cudaGetSymbolAddress((void**)&bqkv,   g_bqkv);
    cudaGetSymbolAddress((void**)&hhi,    g_h_hi);
    cudaGetSymbolAddress((void**)&hlo,    g_h_lo);
    cudaGetSymbolAddress((void**)&atthi,  g_att_hi);
    cudaGetSymbolAddress((void**)&attlo,  g_att_lo);
    cudaGetSymbolAddress((void**)&ffhi,   g_ff_hi);
    cudaGetSymbolAddress((void**)&fflo,   g_ff_lo);
    cudaGetSymbolAddress((void**)&wqkvhi, g_wqkv_hi);
    cudaGetSymbolAddress((void**)&wqkvlo, g_wqkv_lo);
    cudaGetSymbolAddress((void**)&wohi,   g_wo_hi);
    cudaGetSymbolAddress((void**)&wolo,   g_wo_lo);
    cudaGetSymbolAddress((void**)&w1hi,   g_w1_hi);
    cudaGetSymbolAddress((void**)&w1lo,   g_w1_lo);
    cudaGetSymbolAddress((void**)&w2hi,   g_w2_hi);
    cudaGetSymbolAddress((void**)&w2lo,   g_w2_lo);
    cudaGetSymbolAddress((void**)&tokhi,  g_tok_hi);
    cudaGetSymbolAddress((void**)&toklo,  g_tok_lo);

    const int gemmSmem64 = gemm_smem_bytes<64>();
    const int gemmSmem32 = gemm_smem_bytes<32>();
    cudaFuncSetAttribute(bf16x3_gemm<EPI_NONE, 64>,
                         cudaFuncAttributeMaxDynamicSharedMemorySize, gemmSmem64);
    cudaFuncSetAttribute(bf16x3_gemm<EPI_GELU_SPLIT, 64>,
                         cudaFuncAttributeMaxDynamicSharedMemorySize, gemmSmem64);
    cudaFuncSetAttribute(bf16x3_gemm<EPI_RESID, 32>,
                         cudaFuncAttributeMaxDynamicSharedMemorySize, gemmSmem32);
    cudaFuncSetAttribute(attn_mma_kernel,
                         cudaFuncAttributeMaxDynamicSharedMemorySize, ATTN_SMEM_BYTES);

    // ---- prepass ----
    splitT_kernel<<<dim3(D_/32, D_/32, L_), 256>>>(
        wq, wqkvhi, wqkvlo, D_, D_, (size_t)D_*D_, (size_t)QKVN*D_, 0,     D_);
    splitT_kernel<<<dim3(D_/32, D_/32, L_), 256>>>(
        wk, wqkvhi, wqkvlo, D_, D_, (size_t)D_*D_, (size_t)QKVN*D_, D_,    D_);
    splitT_kernel<<<dim3(D_/32, D_/32, L_), 256>>>(
        wv, wqkvhi, wqkvlo, D_, D_, (size_t)D_*D_, (size_t)QKVN*D_, 2*D_,  D_);
    splitT_kernel<<<dim3(D_/32, D_/32, L_), 256>>>(
        wo, wohi, wolo, D_, D_, (size_t)D_*D_, (size_t)D_*D_, 0, D_);
    splitT_kernel<<<dim3(DF_/32, D_/32, L_), 256>>>(
        w1, w1hi, w1lo, D_, DF_, (size_t)D_*DF_, (size_t)DF_*D_, 0, D_);
    splitT_kernel<<<dim3(D_/32, DF_/32, L_), 256>>>(
        w2, w2hi, w2lo, DF_, D_, (size_t)DF_*D_, (size_t)D_*DF_, 0, DF_);
    split_kernel<<<2048, 256>>>(tok, tokhi, toklo, (size_t)V_ * D_);
    bconcat_kernel<<<dim3(3, L_), 256>>>(bq, bk, bv, bqkv);

    embed_kernel<<<M_, 256>>>(ids, tok, pos, x);

    for (int l = 0; l < L_; l++) {
        ln_kernel<<<M_, 256>>>(x, ln1g + l * D_, ln1b + l * D_, hhi, hlo);

        bf16x3_gemm<EPI_NONE, 64><<<dim3(QKVN/64, M_/BM), 256, gemmSmem64>>>(
            hhi, hlo,
            wqkvhi + (size_t)l * QKVN * D_, wqkvlo + (size_t)l * QKVN * D_,
            bqkv + l * QKVN, nullptr, qkv, nullptr, nullptr,
            M_, QKVN, D_, QKVN);

        attn_mma_kernel<<<dim3(8, H_, B_), 128, ATTN_SMEM_BYTES>>>(qkv, atthi, attlo);

        bf16x3_gemm<EPI_RESID, 32><<<dim3(D_/32, M_/BM), 256, gemmSmem32>>>(
            atthi, attlo,
            wohi + (size_t)l * D_ * D_, wolo + (size_t)l * D_ * D_,
            bo + l * D_, x, x, nullptr, nullptr,
            M_, D_, D_, D_);

        ln_kernel<<<M_, 256>>>(x, ln2g + l * D_, ln2b + l * D_, hhi, hlo);

        bf16x3_gemm<EPI_GELU_SPLIT, 64><<<dim3(DF_/64, M_/BM), 256, gemmSmem64>>>(
            hhi, hlo,
            w1hi + (size_t)l * DF_ * D_, w1lo + (size_t)l * DF_ * D_,
            b1 + l * DF_, nullptr, nullptr, ffhi, fflo,
            M_, DF_, D_, DF_);

        bf16x3_gemm<EPI_RESID, 32><<<dim3(D_/32, M_/BM), 256, gemmSmem32>>>(
            ffhi, fflo,
            w2hi + (size_t)l * D_ * DF_, w2lo + (size_t)l * D_ * DF_,
            b2 + l * D_, x, x, nullptr, nullptr,
            M_, D_, DF_, D_);
    }

    ln_kernel<<<M_, 256>>>(x, lnfg, lnfb, hhi, hlo);

    bf16x3_gemm<EPI_NONE, 64><<<dim3((V_ + 63) / 64, M_/BM), 256, gemmSmem64>>>(
        hhi, hlo, tokhi, toklo,
        nullptr, nullptr, out, nullptr, nullptr,
        M_, V_, D_, V_);
}